// round 2
// baseline (speedup 1.0000x reference)
#include <cuda_runtime.h>
#include <cstdint>

// Problem constants
#define O_N 2000
#define T_N 6000
#define DIN 2048
#define DW 300
#define DG 512
#define H_DIM 512
#define L_EXTRA 4
#define E_N (2*T_N)   // 12000 scatter entries

// ---------------- scratch (device globals; no allocation allowed) ----------------
__device__ float g_objA[O_N * DIN];          // initial obj_vecs (O x 2048)
__device__ float g_pred2048[T_N * DIN];      // initial pred_vecs (T x 2048)
__device__ float g_t[T_N * 1536];            // per-layer t = (new_s | new_p | new_o)
__device__ float g_h[T_N * 512];             // hidden buffer (max T x 512)
__device__ float g_pred512[T_N * 512];       // pred_vecs for layers >= 1
__device__ float g_pooled[O_N * 512];
__device__ float g_obj512[O_N * 512];        // obj_vecs for layers >= 1
__device__ int   g_cnt[O_N];
__device__ float g_inv[O_N];
__device__ int   g_off[O_N + 1];
__device__ int   g_objarr[E_N];
__device__ int   g_entries[E_N];

// ---------------- generic fused SGEMM: C = relu(gather(A) @ B + bias) ----------------
// mode 0: A row = A0[row]
// mode 1: A row = [A0[row] (seg) | A1[gidx[row*gstride]] (K-seg)]
// mode 2: A row = [A0[rels[3r]] (seg) | A1[row] (seg) | A0[rels[3r+2]] (K-2seg)]
// Optional aux: copy C[:, aux_lo:aux_hi] to aux (row stride = aux_hi-aux_lo).
__global__ __launch_bounds__(256, 2)
void gemm_kernel(int M, int N, int K, int mode, int seg,
                 const float* __restrict__ A0, int lda0,
                 const float* __restrict__ A1, int lda1,
                 const int* __restrict__ rels,
                 const int* __restrict__ gidx, int gstride,
                 const float* __restrict__ B,
                 const float* __restrict__ bias,
                 float* __restrict__ C, int ldc,
                 float* __restrict__ aux, int aux_lo, int aux_hi)
{
    __shared__ float As[16][128];
    __shared__ float Bs[16][128];
    const int bm = blockIdx.y * 128;
    const int bn = blockIdx.x * 128;
    const int tid = threadIdx.x;
    const int tx = tid & 15, ty = tid >> 4;

    // A-tile load mapping: thread -> (row am, k-offset ak), 8 contiguous k each
    const int am = tid >> 1;
    const int ak = (tid & 1) * 8;
    const int arow = bm + am;
    // B-tile load mapping: thread -> (k row bk, 8 contiguous n)
    const int bk = tid >> 4;
    const int bn8 = (tid & 15) * 8;

    const float* Arow0 = A0;
    const float* Arow1 = A1;
    const float* Arow2 = A0;
    const bool rvalid = (arow < M);
    if (rvalid) {
        if (mode == 2) {
            int is = rels[3 * arow];
            int io = rels[3 * arow + 2];
            Arow0 = A0 + (size_t)is * lda0;
            Arow1 = A1 + (size_t)arow * lda1;
            Arow2 = A0 + (size_t)io * lda0;
        } else if (mode == 1) {
            int g = gidx[(size_t)arow * gstride];
            Arow0 = A0 + (size_t)arow * lda0;
            Arow1 = A1 + (size_t)g * lda1;
        } else {
            Arow0 = A0 + (size_t)arow * lda0;
        }
    }

    float acc[8][8] = {};

    for (int k0 = 0; k0 < K; k0 += 16) {
        // A tile (scalar loads — gather modes break contiguity)
        #pragma unroll
        for (int j = 0; j < 8; j++) {
            int k = k0 + ak + j;
            float v = 0.f;
            if (rvalid && k < K) {
                if (mode == 2) {
                    v = (k < seg) ? Arow0[k]
                      : (k < 2 * seg) ? Arow1[k - seg]
                      : Arow2[k - 2 * seg];
                } else if (mode == 1) {
                    v = (k < seg) ? Arow0[k] : Arow1[k - seg];
                } else {
                    v = Arow0[k];
                }
            }
            As[ak + j][am] = v;
        }
        // B tile (vectorized; N is always a multiple of 128)
        {
            int k = k0 + bk;
            float4 b0 = make_float4(0.f, 0.f, 0.f, 0.f);
            float4 b1 = make_float4(0.f, 0.f, 0.f, 0.f);
            if (k < K) {
                const float4* p = reinterpret_cast<const float4*>(B + (size_t)k * N + bn + bn8);
                b0 = p[0]; b1 = p[1];
            }
            *reinterpret_cast<float4*>(&Bs[bk][bn8])     = b0;
            *reinterpret_cast<float4*>(&Bs[bk][bn8 + 4]) = b1;
        }
        __syncthreads();

        #pragma unroll
        for (int kk = 0; kk < 16; kk++) {
            float a[8], b[8];
            #pragma unroll
            for (int i = 0; i < 8; i++) a[i] = As[kk][ty * 8 + i];
            #pragma unroll
            for (int j = 0; j < 8; j++) b[j] = Bs[kk][tx * 8 + j];
            #pragma unroll
            for (int i = 0; i < 8; i++)
                #pragma unroll
                for (int j = 0; j < 8; j++)
                    acc[i][j] = fmaf(a[i], b[j], acc[i][j]);
        }
        __syncthreads();
    }

    const int awidth = aux_hi - aux_lo;
    #pragma unroll
    for (int i = 0; i < 8; i++) {
        int row = bm + ty * 8 + i;
        if (row >= M) continue;
        #pragma unroll
        for (int j = 0; j < 8; j++) {
            int col = bn + tx * 8 + j;
            float v = fmaxf(acc[i][j] + bias[col], 0.f);
            C[(size_t)row * ldc + col] = v;
            if (aux != nullptr && col >= aux_lo && col < aux_hi)
                aux[(size_t)row * awidth + (col - aux_lo)] = v;
        }
    }
}

// ---------------- deterministic scatter-mean pooling (CSR built once per launch) ----------------
__global__ void zero_int_kernel(int* p, int n) {
    int i = blockIdx.x * blockDim.x + threadIdx.x;
    if (i < n) p[i] = 0;
}

// entry e = 2*t + r (r=0 -> s, r=1 -> o). Record object id; count per object (int atomics = deterministic).
__global__ void build_count_kernel(const int* __restrict__ rels, int* __restrict__ objarr, int* __restrict__ cnt) {
    int e = blockIdx.x * blockDim.x + threadIdx.x;
    if (e >= E_N) return;
    int t = e >> 1;
    int v = rels[3 * t + ((e & 1) ? 2 : 0)];
    objarr[e] = v;
    atomicAdd(&cnt[v], 1);
}

// exclusive scan over cnt (O_N <= 2048), plus inv = 1/max(cnt,1). One block of 1024.
__global__ void scan_kernel(const int* __restrict__ cnt, int* __restrict__ off, float* __restrict__ inv) {
    __shared__ int buf[2][2048];
    int tid = threadIdx.x;
    for (int i = tid; i < 2048; i += 1024) {
        int c = (i < O_N) ? cnt[i] : 0;
        buf[0][i] = c;
        if (i < O_N) inv[i] = 1.0f / fmaxf((float)c, 1.0f);
    }
    __syncthreads();
    int src = 0;
    for (int d = 1; d < 2048; d <<= 1) {
        for (int i = tid; i < 2048; i += 1024) {
            int v = buf[src][i];
            if (i >= d) v += buf[src][i - d];
            buf[1 - src][i] = v;
        }
        src = 1 - src;
        __syncthreads();
    }
    for (int i = tid; i < O_N; i += 1024) off[i] = (i == 0) ? 0 : buf[src][i - 1];
    if (tid == 0) off[O_N] = buf[src][O_N - 1];
}

// deterministic rank within each object's entry list (triple order preserved)
__global__ void rank_fill_kernel(const int* __restrict__ objarr, const int* __restrict__ off,
                                 int* __restrict__ entries) {
    int e = blockIdx.x * blockDim.x + threadIdx.x;
    if (e >= E_N) return;
    int v = objarr[e];
    int rank = 0;
    for (int j = 0; j < e; j++) rank += (objarr[j] == v);
    entries[off[v] + rank] = e;
}

// pooled[i] = inv[i] * sum over entries of t[triple, (role? 1024:0) + c]; deterministic order
__global__ void pool_gather_kernel(const float* __restrict__ t,
                                   const int* __restrict__ entries, const int* __restrict__ off,
                                   const float* __restrict__ inv, float* __restrict__ pooled) {
    int i = blockIdx.x;                 // object
    int c0 = threadIdx.x;               // cols c0 and c0+256
    int beg = off[i], end = off[i + 1];
    float s0 = 0.f, s1 = 0.f;
    for (int p = beg; p < end; p++) {
        int e = entries[p];
        int tr = e >> 1;
        const float* src = t + (size_t)tr * 1536 + ((e & 1) ? 1024 : 0);
        s0 += src[c0];
        s1 += src[c0 + 256];
    }
    float iv = inv[i];
    pooled[(size_t)i * 512 + c0]       = s0 * iv;
    pooled[(size_t)i * 512 + c0 + 256] = s1 * iv;
}

// ---------------- host-side glue ----------------
static inline void run_gemm(int M, int N, int K, int mode, int seg,
                            const float* A0, int lda0, const float* A1, int lda1,
                            const int* rels, const int* gidx, int gstride,
                            const float* B, const float* bias,
                            float* C, int ldc,
                            float* aux = nullptr, int aux_lo = 0, int aux_hi = 0)
{
    dim3 grid(N / 128, (M + 127) / 128);
    gemm_kernel<<<grid, 256>>>(M, N, K, mode, seg, A0, lda0, A1, lda1, rels, gidx, gstride,
                               B, bias, C, ldc, aux, aux_lo, aux_hi);
}

extern "C" void kernel_launch(void* const* d_in, const int* in_sizes, int n_in,
                              void* d_out, int out_size)
{
    const float* obj_embs  = (const float*)d_in[0];
    const float* pred_embs = (const float*)d_in[2];
    const int*   rels      = (const int*)d_in[4];
    const int*   objs      = (const int*)d_in[5];
    const float* obj_table = (const float*)d_in[6];
    const float* rel_table = (const float*)d_in[7];
    const float* Wf_obj    = (const float*)d_in[8];
    const float* bf_obj    = (const float*)d_in[9];
    const float* Wf_rel    = (const float*)d_in[10];
    const float* bf_rel    = (const float*)d_in[11];
    const float* W1a       = (const float*)d_in[12];
    const float* b1a       = (const float*)d_in[13];
    const float* W1b       = (const float*)d_in[14];
    const float* b1b       = (const float*)d_in[15];
    const float* W2a       = (const float*)d_in[16];
    const float* b2a       = (const float*)d_in[17];
    const float* W2b       = (const float*)d_in[18];
    const float* b2b       = (const float*)d_in[19];
    const float* Ws1a      = (const float*)d_in[20];
    const float* bs1a      = (const float*)d_in[21];
    const float* Ws1b      = (const float*)d_in[22];
    const float* bs1b      = (const float*)d_in[23];
    const float* Ws2a      = (const float*)d_in[24];
    const float* bs2a      = (const float*)d_in[25];
    const float* Ws2b      = (const float*)d_in[26];
    const float* bs2b      = (const float*)d_in[27];
    float* out = (float*)d_out;

    float *objA, *pred2048, *tbuf, *hbuf, *pred512, *pooled, *obj512, *finv;
    int *cnt, *off, *objarr, *entries;
    cudaGetSymbolAddress((void**)&objA,     g_objA);
    cudaGetSymbolAddress((void**)&pred2048, g_pred2048);
    cudaGetSymbolAddress((void**)&tbuf,     g_t);
    cudaGetSymbolAddress((void**)&hbuf,     g_h);
    cudaGetSymbolAddress((void**)&pred512,  g_pred512);
    cudaGetSymbolAddress((void**)&pooled,   g_pooled);
    cudaGetSymbolAddress((void**)&obj512,   g_obj512);
    cudaGetSymbolAddress((void**)&finv,     g_inv);
    cudaGetSymbolAddress((void**)&cnt,      g_cnt);
    cudaGetSymbolAddress((void**)&off,      g_off);
    cudaGetSymbolAddress((void**)&objarr,   g_objarr);
    cudaGetSymbolAddress((void**)&entries,  g_entries);

    // --- CSR for deterministic pooling (indices are fixed across layers) ---
    zero_int_kernel<<<(O_N + 255) / 256, 256>>>(cnt, O_N);
    build_count_kernel<<<(E_N + 255) / 256, 256>>>(rels, objarr, cnt);
    scan_kernel<<<1, 1024>>>(cnt, off, finv);
    rank_fill_kernel<<<(E_N + 255) / 256, 256>>>(objarr, off, entries);

    // --- initial embedding GEMMs (fused concat + table gather) ---
    // obj_vecs = relu([obj_embs | obj_table[objs]] @ Wf_obj + bf_obj)
    run_gemm(O_N, DIN, DIN + DW, /*mode=*/1, /*seg=*/DIN,
             obj_embs, DIN, obj_table, DW, nullptr, objs, 1,
             Wf_obj, bf_obj, objA, DIN);
    // pred_vecs = relu([pred_embs | rel_table[rels[:,1]]] @ Wf_rel + bf_rel)
    run_gemm(T_N, DIN, DIN + DW, 1, DIN,
             pred_embs, DIN, rel_table, DW, nullptr, rels + 1, 3,
             Wf_rel, bf_rel, pred2048, DIN);

    // --- layer 0 (K = 3*2048) ---
    run_gemm(T_N, H_DIM, 3 * DIN, /*mode=*/2, /*seg=*/DIN,
             objA, DIN, pred2048, DIN, rels, nullptr, 0,
             W1a, b1a, hbuf, H_DIM);
    run_gemm(T_N, 1536, H_DIM, 0, 0,
             hbuf, H_DIM, nullptr, 0, nullptr, nullptr, 0,
             W1b, b1b, tbuf, 1536, pred512, 512, 1024);
    pool_gather_kernel<<<O_N, 256>>>(tbuf, entries, off, finv, pooled);
    run_gemm(O_N, H_DIM, H_DIM, 0, 0, pooled, 512, nullptr, 0, nullptr, nullptr, 0,
             W2a, b2a, hbuf, H_DIM);
    run_gemm(O_N, DG, H_DIM, 0, 0, hbuf, 512, nullptr, 0, nullptr, nullptr, 0,
             W2b, b2b, obj512, DG);

    // --- extra layers (K = 3*512) ---
    for (int i = 0; i < L_EXTRA; i++) {
        const bool last = (i == L_EXTRA - 1);
        float* obj_dst  = last ? out : obj512;
        float* pred_dst = last ? (out + (size_t)O_N * DG) : pred512;

        run_gemm(T_N, H_DIM, 3 * DG, 2, DG,
                 obj512, DG, pred512, DG, rels, nullptr, 0,
                 Ws1a + (size_t)i * 3 * DG * H_DIM, bs1a + (size_t)i * H_DIM,
                 hbuf, H_DIM);
        run_gemm(T_N, 1536, H_DIM, 0, 0,
                 hbuf, H_DIM, nullptr, 0, nullptr, nullptr, 0,
                 Ws1b + (size_t)i * H_DIM * 1536, bs1b + (size_t)i * 1536,
                 tbuf, 1536, pred_dst, 512, 1024);
        pool_gather_kernel<<<O_N, 256>>>(tbuf, entries, off, finv, pooled);
        run_gemm(O_N, H_DIM, H_DIM, 0, 0, pooled, 512, nullptr, 0, nullptr, nullptr, 0,
                 Ws2a + (size_t)i * H_DIM * H_DIM, bs2a + (size_t)i * H_DIM,
                 hbuf, H_DIM);
        run_gemm(O_N, DG, H_DIM, 0, 0, hbuf, 512, nullptr, 0, nullptr, nullptr, 0,
                 Ws2b + (size_t)i * H_DIM * DG, bs2b + (size_t)i * DG,
                 obj_dst, DG);
    }
}

// round 4
// speedup vs baseline: 2.4469x; 2.4469x over previous
#include <cuda_runtime.h>
#include <cuda_bf16.h>
#include <cstdint>

#define O_N 2000
#define T_N 6000
#define DIN 2048
#define DW 300
#define DG 512
#define H_DIM 512
#define L_EXTRA 4
#define E_N (2*T_N)

#define BM 128
#define BN 128
#define BKG 32          // gmem k per chunk (fp32)
#define BKS 96          // smem k per chunk (bf16, 3x split)
#define ASTRIDE_B 208   // (96+8) bf16 * 2 bytes, 16B aligned, conflict-free
#define ABUF_B (128*ASTRIDE_B)
#define SM_TOTAL (4*ABUF_B)   // A0,A1,B0,B1 = 106496

// ---------------- scratch (device globals; no allocation allowed) ----------------
__device__ __align__(16) float g_objA[O_N * DIN];
__device__ __align__(16) float g_pred2048[T_N * DIN];
__device__ __align__(16) float g_t[T_N * 1536];
__device__ __align__(16) float g_h[T_N * 512];
__device__ __align__(16) float g_pred512[T_N * 512];
__device__ __align__(16) float g_pooled[O_N * 512];
__device__ __align__(16) float g_obj512[O_N * 512];
__device__ int   g_cnt[O_N];
__device__ float g_inv[O_N];
__device__ int   g_off[O_N + 1];
__device__ int   g_objarr[E_N];
__device__ int   g_entries[E_N];
#define WT_POOL 22462464
__device__ __align__(16) float g_wt[WT_POOL];   // transposed weights [N,K] K-major fp32

// ---------------- PTX helpers ----------------
__device__ __forceinline__ uint32_t smem_u32(const void* p) {
    uint32_t a;
    asm("{ .reg .u64 t; cvta.to.shared.u64 t, %1; cvt.u32.u64 %0, t; }" : "=r"(a) : "l"(p));
    return a;
}
__device__ __forceinline__ void ldsm4(uint32_t* r, uint32_t addr) {
    asm volatile("ldmatrix.sync.aligned.m8n8.x4.shared.b16 {%0,%1,%2,%3}, [%4];"
        : "=r"(r[0]), "=r"(r[1]), "=r"(r[2]), "=r"(r[3]) : "r"(addr));
}
__device__ __forceinline__ void mma16816(float* d, const uint32_t* a, const uint32_t* b) {
    asm volatile("mma.sync.aligned.m16n8k16.row.col.f32.bf16.bf16.f32 "
        "{%0,%1,%2,%3}, {%4,%5,%6,%7}, {%8,%9}, {%0,%1,%2,%3};"
        : "+f"(d[0]), "+f"(d[1]), "+f"(d[2]), "+f"(d[3])
        : "r"(a[0]), "r"(a[1]), "r"(a[2]), "r"(a[3]), "r"(b[0]), "r"(b[1]));
}
__device__ __forceinline__ void sts64(uint32_t a, uint32_t v0, uint32_t v1) {
    asm volatile("st.shared.v2.b32 [%0], {%1, %2};" :: "r"(a), "r"(v0), "r"(v1) : "memory");
}
// split float4 -> packed bf16 hi pair-regs and lo pair-regs
__device__ __forceinline__ void split4(float4 v, uint32_t* hi, uint32_t* lo) {
    __nv_bfloat162 h01 = __floats2bfloat162_rn(v.x, v.y);
    __nv_bfloat162 h23 = __floats2bfloat162_rn(v.z, v.w);
    float r0 = v.x - __bfloat162float(h01.x);
    float r1 = v.y - __bfloat162float(h01.y);
    float r2 = v.z - __bfloat162float(h23.x);
    float r3 = v.w - __bfloat162float(h23.y);
    __nv_bfloat162 l01 = __floats2bfloat162_rn(r0, r1);
    __nv_bfloat162 l23 = __floats2bfloat162_rn(r2, r3);
    hi[0] = *(uint32_t*)&h01; hi[1] = *(uint32_t*)&h23;
    lo[0] = *(uint32_t*)&l01; lo[1] = *(uint32_t*)&l23;
}

// ---------------- bf16x3 mma.sync GEMM: C = relu(gather(A) @ Bt^T + bias) ----------------
// Bt: [Ntot, K] K-major fp32 (pre-transposed weights)
// mode 0: A row = A0[row]
// mode 1: A row = [A0[row] | A1[gidx[row*gstride]]]
// mode 2: A row = [A0[rels[3r]] | A1[row] | A0[rels[3r+2]]]
__global__ __launch_bounds__(256, 1)
void mma_gemm_kernel(int M, int K, int mode, int seg,
                     const float* __restrict__ A0, int lda0,
                     const float* __restrict__ A1, int lda1,
                     const int* __restrict__ rels,
                     const int* __restrict__ gidx, int gstride,
                     const float* __restrict__ Bt,
                     const float* __restrict__ bias,
                     float* __restrict__ C, int ldc,
                     float* __restrict__ aux, int aux_lo, int aux_hi)
{
    extern __shared__ char smem[];
    const uint32_t sb = smem_u32(smem);
    const int tid = threadIdx.x;
    const int lane = tid & 31;
    const int wid = tid >> 5;
    const int bm = blockIdx.y * BM;
    const int bn = blockIdx.x * BN;

    // ---- per-thread loader geometry (fixed) ----
    const int q = tid & 7;            // k-quad within chunk: k_local = q*4
    const int rbase = tid >> 3;       // row 0..31; +32 per i
    // A gather row pointers per i
    const float* pa0[4]; const float* pa1[4]; const float* pa2[4];
    bool av[4];
    #pragma unroll
    for (int i = 0; i < 4; i++) {
        int r = rbase + i * 32;
        int arow = bm + r;
        av[i] = (arow < M);
        pa0[i] = pa1[i] = pa2[i] = A0;
        if (av[i]) {
            if (mode == 2) {
                pa0[i] = A0 + (size_t)rels[3 * arow] * lda0;
                pa1[i] = A1 + (size_t)arow * lda1;
                pa2[i] = A0 + (size_t)rels[3 * arow + 2] * lda0;
            } else if (mode == 1) {
                pa0[i] = A0 + (size_t)arow * lda0;
                pa1[i] = A1 + (size_t)gidx[(size_t)arow * gstride] * lda1;
            } else {
                pa0[i] = A0 + (size_t)arow * lda0;
            }
        }
    }
    const float* pb0 = Bt + (size_t)(bn + rbase) * K;
    const size_t bstep = (size_t)32 * K;

    // ---- accumulators ----
    float acc[4][4][4];
    #pragma unroll
    for (int a = 0; a < 4; a++)
        #pragma unroll
        for (int b = 0; b < 4; b++)
            #pragma unroll
            for (int c = 0; c < 4; c++) acc[a][b][c] = 0.f;

    // warp tile position
    const int wr = wid & 1;     // 0..1 -> 64-row block
    const int wc = wid >> 1;    // 0..3 -> 32-col block

    // ldmatrix lane offsets
    const uint32_t a_l_off = (uint32_t)((lane & 15) * ASTRIDE_B + (lane >> 4) * 16);
    const uint32_t b_l_off = (uint32_t)((((lane & 7) + ((lane >> 4) << 3)) * ASTRIDE_B) + (((lane >> 3) & 1) << 4));

    const int NT = (K + BKG - 1) / BKG;

    float4 ra[4], rb[4];
    // prefetch chunk 0
    {
        int k = q * 4;
        #pragma unroll
        for (int i = 0; i < 4; i++) {
            ra[i] = make_float4(0.f, 0.f, 0.f, 0.f);
            if (av[i] && k < K) {
                const float* p;
                if (mode == 2)      p = (k < seg) ? pa0[i] + k : (k < 2*seg) ? pa1[i] + (k - seg) : pa2[i] + (k - 2*seg);
                else if (mode == 1) p = (k < seg) ? pa0[i] + k : pa1[i] + (k - seg);
                else                p = pa0[i] + k;
                ra[i] = *reinterpret_cast<const float4*>(p);
            }
            rb[i] = make_float4(0.f, 0.f, 0.f, 0.f);
            if (k < K) rb[i] = *reinterpret_cast<const float4*>(pb0 + (size_t)i * bstep + k);
        }
    }

    for (int it = 0; it < NT; it++) {
        const int p = it & 1;
        const uint32_t abuf = sb + (uint32_t)p * ABUF_B;
        const uint32_t bbuf = sb + (uint32_t)(2 + p) * ABUF_B;

        // convert + STS (segments: A=[ah|al|ah], B=[bh|bh|bl])
        #pragma unroll
        for (int i = 0; i < 4; i++) {
            uint32_t hi[2], lo[2];
            split4(ra[i], hi, lo);
            uint32_t base = abuf + (uint32_t)((rbase + i * 32) * ASTRIDE_B + q * 8);
            sts64(base,       hi[0], hi[1]);
            sts64(base + 64,  lo[0], lo[1]);
            sts64(base + 128, hi[0], hi[1]);
            split4(rb[i], hi, lo);
            base = bbuf + (uint32_t)((rbase + i * 32) * ASTRIDE_B + q * 8);
            sts64(base,       hi[0], hi[1]);
            sts64(base + 64,  hi[0], hi[1]);
            sts64(base + 128, lo[0], lo[1]);
        }
        __syncthreads();

        // prefetch next chunk
        if (it + 1 < NT) {
            int k = (it + 1) * BKG + q * 4;
            #pragma unroll
            for (int i = 0; i < 4; i++) {
                ra[i] = make_float4(0.f, 0.f, 0.f, 0.f);
                if (av[i] && k < K) {
                    const float* p2;
                    if (mode == 2)      p2 = (k < seg) ? pa0[i] + k : (k < 2*seg) ? pa1[i] + (k - seg) : pa2[i] + (k - 2*seg);
                    else if (mode == 1) p2 = (k < seg) ? pa0[i] + k : pa1[i] + (k - seg);
                    else                p2 = pa0[i] + k;
                    ra[i] = *reinterpret_cast<const float4*>(p2);
                }
                rb[i] = make_float4(0.f, 0.f, 0.f, 0.f);
                if (k < K) rb[i] = *reinterpret_cast<const float4*>(pb0 + (size_t)i * bstep + k);
            }
        }

        // mma over 96 bf16 k (6 ksteps of 16)
        const uint32_t abase = abuf + (uint32_t)(wr * 64 * ASTRIDE_B) + a_l_off;
        const uint32_t bbase = bbuf + (uint32_t)(wc * 32 * ASTRIDE_B) + b_l_off;
        #pragma unroll
        for (int ks = 0; ks < 6; ks++) {
            const uint32_t kb = ks * 32;   // 16 bf16 = 32 bytes
            uint32_t af[4][4], bf[2][4];
            #pragma unroll
            for (int mt = 0; mt < 4; mt++)
                ldsm4(af[mt], abase + (uint32_t)(mt * 16 * ASTRIDE_B) + kb);
            #pragma unroll
            for (int np = 0; np < 2; np++)
                ldsm4(bf[np], bbase + (uint32_t)(np * 16 * ASTRIDE_B) + kb);
            #pragma unroll
            for (int mt = 0; mt < 4; mt++) {
                #pragma unroll
                for (int np = 0; np < 2; np++) {
                    mma16816(acc[mt][2 * np],     af[mt], &bf[np][0]);
                    mma16816(acc[mt][2 * np + 1], af[mt], &bf[np][2]);
                }
            }
        }
        __syncthreads();
    }

    // ---- epilogue: bias + relu + store (and aux slice) ----
    const int g = lane >> 2, qr = lane & 3;
    const int awidth = aux_hi - aux_lo;
    #pragma unroll
    for (int nt = 0; nt < 4; nt++) {
        const int col = bn + wc * 32 + nt * 8 + qr * 2;
        const float2 bv = *reinterpret_cast<const float2*>(bias + col);
        const bool do_aux = (aux != nullptr) && (col >= aux_lo) && (col < aux_hi);
        #pragma unroll
        for (int mt = 0; mt < 4; mt++) {
            const int row0 = bm + wr * 64 + mt * 16 + g;
            float v0 = fmaxf(acc[mt][nt][0] + bv.x, 0.f);
            float v1 = fmaxf(acc[mt][nt][1] + bv.y, 0.f);
            float v2 = fmaxf(acc[mt][nt][2] + bv.x, 0.f);
            float v3 = fmaxf(acc[mt][nt][3] + bv.y, 0.f);
            if (row0 < M) {
                *reinterpret_cast<float2*>(C + (size_t)row0 * ldc + col) = make_float2(v0, v1);
                if (do_aux)
                    *reinterpret_cast<float2*>(aux + (size_t)row0 * awidth + (col - aux_lo)) = make_float2(v0, v1);
            }
            if (row0 + 8 < M) {
                *reinterpret_cast<float2*>(C + (size_t)(row0 + 8) * ldc + col) = make_float2(v2, v3);
                if (do_aux)
                    *reinterpret_cast<float2*>(aux + (size_t)(row0 + 8) * awidth + (col - aux_lo)) = make_float2(v2, v3);
            }
        }
    }
}

// ---------------- weight transpose: Bt[n*K+k] = B[k*N+n] ----------------
__global__ void transpose_kernel(const float* __restrict__ B, float* __restrict__ Bt,
                                 int K, int N) {
    __shared__ float tile[32][33];
    int bk = blockIdx.x * 32, bn = blockIdx.y * 32;
    int x = threadIdx.x, y = threadIdx.y;
    for (int i = y; i < 32; i += 8) {
        int k = bk + i, n = bn + x;
        tile[i][x] = (k < K && n < N) ? B[(size_t)k * N + n] : 0.f;
    }
    __syncthreads();
    for (int i = y; i < 32; i += 8) {
        int n = bn + i, k = bk + x;
        if (n < N && k < K) Bt[(size_t)n * K + k] = tile[x][i];
    }
}

// ---------------- deterministic scatter-mean pooling ----------------
__global__ void zero_int_kernel(int* p, int n) {
    int i = blockIdx.x * blockDim.x + threadIdx.x;
    if (i < n) p[i] = 0;
}
__global__ void build_count_kernel(const int* __restrict__ rels, int* __restrict__ objarr,
                                   int* __restrict__ cnt) {
    int e = blockIdx.x * blockDim.x + threadIdx.x;
    if (e >= E_N) return;
    int t = e >> 1;
    int v = rels[3 * t + ((e & 1) ? 2 : 0)];
    objarr[e] = v;
    atomicAdd(&cnt[v], 1);
}
__global__ void scan_kernel(const int* __restrict__ cnt, int* __restrict__ off,
                            float* __restrict__ inv) {
    __shared__ int buf[2][2048];
    int tid = threadIdx.x;
    for (int i = tid; i < 2048; i += 1024) {
        int c = (i < O_N) ? cnt[i] : 0;
        buf[0][i] = c;
        if (i < O_N) inv[i] = 1.0f / fmaxf((float)c, 1.0f);
    }
    __syncthreads();
    int src = 0;
    for (int d = 1; d < 2048; d <<= 1) {
        for (int i = tid; i < 2048; i += 1024) {
            int v = buf[src][i];
            if (i >= d) v += buf[src][i - d];
            buf[1 - src][i] = v;
        }
        src = 1 - src;
        __syncthreads();
    }
    for (int i = tid; i < O_N; i += 1024) off[i] = (i == 0) ? 0 : buf[src][i - 1];
    if (tid == 0) off[O_N] = buf[src][O_N - 1];
}
// deterministic per-object scan, O(O*E)
__global__ void rank_fill_kernel(const int* __restrict__ objarr, const int* __restrict__ off,
                                 int* __restrict__ entries) {
    int i = blockIdx.x * blockDim.x + threadIdx.x;
    if (i >= O_N) return;
    int w = off[i];
    for (int e = 0; e < E_N; e++)
        if (objarr[e] == i) entries[w++] = e;
}
__global__ void pool_gather_kernel(const float* __restrict__ t,
                                   const int* __restrict__ entries, const int* __restrict__ off,
                                   const float* __restrict__ inv, float* __restrict__ pooled) {
    int i = blockIdx.x;
    int c0 = threadIdx.x;
    int beg = off[i], end = off[i + 1];
    float s0 = 0.f, s1 = 0.f;
    for (int p = beg; p < end; p++) {
        int e = entries[p];
        int tr = e >> 1;
        const float* src = t + (size_t)tr * 1536 + ((e & 1) ? 1024 : 0);
        s0 += src[c0];
        s1 += src[c0 + 256];
    }
    float iv = inv[i];
    pooled[(size_t)i * 512 + c0]       = s0 * iv;
    pooled[(size_t)i * 512 + c0 + 256] = s1 * iv;
}

// ---------------- host glue ----------------
static inline void run_mma(int M, int Ntot, int K, int mode, int seg,
                           const float* A0, int lda0, const float* A1, int lda1,
                           const int* rels, const int* gidx, int gstride,
                           const float* Bt, const float* bias,
                           float* C, int ldc,
                           float* aux = nullptr, int aux_lo = 0, int aux_hi = 0)
{
    dim3 grid(Ntot / BN, (M + BM - 1) / BM);
    mma_gemm_kernel<<<grid, 256, SM_TOTAL>>>(M, K, mode, seg, A0, lda0, A1, lda1,
                                             rels, gidx, gstride, Bt, bias, C, ldc,
                                             aux, aux_lo, aux_hi);
}
static inline void run_transpose(const float* B, float* Bt, int K, int N) {
    dim3 grid((K + 31) / 32, (N + 31) / 32);
    transpose_kernel<<<grid, dim3(32, 8)>>>(B, Bt, K, N);
}

extern "C" void kernel_launch(void* const* d_in, const int* in_sizes, int n_in,
                              void* d_out, int out_size)
{
    const float* obj_embs  = (const float*)d_in[0];
    const float* pred_embs = (const float*)d_in[2];
    const int*   rels      = (const int*)d_in[4];
    const int*   objs      = (const int*)d_in[5];
    const float* obj_table = (const float*)d_in[6];
    const float* rel_table = (const float*)d_in[7];
    const float* Wf_obj    = (const float*)d_in[8];
    const float* bf_obj    = (const float*)d_in[9];
    const float* Wf_rel    = (const float*)d_in[10];
    const float* bf_rel    = (const float*)d_in[11];
    const float* W1a       = (const float*)d_in[12];
    const float* b1a       = (const float*)d_in[13];
    const float* W1b       = (const float*)d_in[14];
    const float* b1b       = (const float*)d_in[15];
    const float* W2a       = (const float*)d_in[16];
    const float* b2a       = (const float*)d_in[17];
    const float* W2b       = (const float*)d_in[18];
    const float* b2b       = (const float*)d_in[19];
    const float* Ws1a      = (const float*)d_in[20];
    const float* bs1a      = (const float*)d_in[21];
    const float* Ws1b      = (const float*)d_in[22];
    const float* bs1b      = (const float*)d_in[23];
    const float* Ws2a      = (const float*)d_in[24];
    const float* bs2a      = (const float*)d_in[25];
    const float* Ws2b      = (const float*)d_in[26];
    const float* bs2b      = (const float*)d_in[27];
    float* out = (float*)d_out;

    cudaFuncSetAttribute(mma_gemm_kernel, cudaFuncAttributeMaxDynamicSharedMemorySize, SM_TOTAL);

    float *objA, *pred2048, *tbuf, *hbuf, *pred512, *pooled, *obj512, *finv, *wt;
    int *cnt, *off, *objarr, *entries;
    cudaGetSymbolAddress((void**)&objA,     g_objA);
    cudaGetSymbolAddress((void**)&pred2048, g_pred2048);
    cudaGetSymbolAddress((void**)&tbuf,     g_t);
    cudaGetSymbolAddress((void**)&hbuf,     g_h);
    cudaGetSymbolAddress((void**)&pred512,  g_pred512);
    cudaGetSymbolAddress((void**)&pooled,   g_pooled);
    cudaGetSymbolAddress((void**)&obj512,   g_obj512);
    cudaGetSymbolAddress((void**)&finv,     g_inv);
    cudaGetSymbolAddress((void**)&wt,       g_wt);
    cudaGetSymbolAddress((void**)&cnt,      g_cnt);
    cudaGetSymbolAddress((void**)&off,      g_off);
    cudaGetSymbolAddress((void**)&objarr,   g_objarr);
    cudaGetSymbolAddress((void**)&entries,  g_entries);

    // transposed weight pool offsets
    size_t po = 0;
    float* tWfobj = wt + po; po += (size_t)DIN * (DIN + DW);
    float* tWfrel = wt + po; po += (size_t)DIN * (DIN + DW);
    float* tW1a   = wt + po; po += (size_t)H_DIM * (3 * DIN);
    float* tW1b   = wt + po; po += (size_t)1536 * H_DIM;
    float* tW2a   = wt + po; po += (size_t)H_DIM * H_DIM;
    float* tW2b   = wt + po; po += (size_t)DG * H_DIM;
    float* tWs1a  = wt + po; po += (size_t)L_EXTRA * H_DIM * (3 * DG);
    float* tWs1b  = wt + po; po += (size_t)L_EXTRA * 1536 * H_DIM;
    float* tWs2a  = wt + po; po += (size_t)L_EXTRA * H_DIM * H_DIM;
    float* tWs2b  = wt + po; po += (size_t)L_EXTRA * DG * H_DIM;

    // --- weight transposes ([K,N] -> [N,K]) ---
    run_transpose(Wf_obj, tWfobj, DIN + DW, DIN);
    run_transpose(Wf_rel, tWfrel, DIN + DW, DIN);
    run_transpose(W1a, tW1a, 3 * DIN, H_DIM);
    run_transpose(W1b, tW1b, H_DIM, 1536);
    run_transpose(W2a, tW2a, H_DIM, H_DIM);
    run_transpose(W2b, tW2b, H_DIM, DG);
    for (int i = 0; i < L_EXTRA; i++) {
        run_transpose(Ws1a + (size_t)i * 3 * DG * H_DIM, tWs1a + (size_t)i * H_DIM * 3 * DG, 3 * DG, H_DIM);
        run_transpose(Ws1b + (size_t)i * H_DIM * 1536,   tWs1b + (size_t)i * 1536 * H_DIM,   H_DIM, 1536);
        run_transpose(Ws2a + (size_t)i * H_DIM * H_DIM,  tWs2a + (size_t)i * H_DIM * H_DIM,  H_DIM, H_DIM);
        run_transpose(Ws2b + (size_t)i * H_DIM * DG,     tWs2b + (size_t)i * DG * H_DIM,     H_DIM, DG);
    }

    // --- CSR for deterministic pooling ---
    zero_int_kernel<<<(O_N + 255) / 256, 256>>>(cnt, O_N);
    build_count_kernel<<<(E_N + 255) / 256, 256>>>(rels, objarr, cnt);
    scan_kernel<<<1, 1024>>>(cnt, off, finv);
    rank_fill_kernel<<<(O_N + 255) / 256, 256>>>(objarr, off, entries);

    // --- initial embedding GEMMs ---
    run_mma(O_N, DIN, DIN + DW, 1, DIN,
            obj_embs, DIN, obj_table, DW, nullptr, objs, 1,
            tWfobj, bf_obj, objA, DIN);
    run_mma(T_N, DIN, DIN + DW, 1, DIN,
            pred_embs, DIN, rel_table, DW, nullptr, rels + 1, 3,
            tWfrel, bf_rel, pred2048, DIN);

    // --- layer 0 ---
    run_mma(T_N, H_DIM, 3 * DIN, 2, DIN,
            objA, DIN, pred2048, DIN, rels, nullptr, 0,
            tW1a, b1a, hbuf, H_DIM);
    run_mma(T_N, 1536, H_DIM, 0, 0,
            hbuf, H_DIM, nullptr, 0, nullptr, nullptr, 0,
            tW1b, b1b, tbuf, 1536, pred512, 512, 1024);
    pool_gather_kernel<<<O_N, 256>>>(tbuf, entries, off, finv, pooled);
    run_mma(O_N, H_DIM, H_DIM, 0, 0, pooled, 512, nullptr, 0, nullptr, nullptr, 0,
            tW2a, b2a, hbuf, H_DIM);
    run_mma(O_N, DG, H_DIM, 0, 0, hbuf, 512, nullptr, 0, nullptr, nullptr, 0,
            tW2b, b2b, obj512, DG);

    // --- extra layers ---
    for (int i = 0; i < L_EXTRA; i++) {
        const bool last = (i == L_EXTRA - 1);
        float* obj_dst  = last ? out : obj512;
        float* pred_dst = last ? (out + (size_t)O_N * DG) : pred512;

        run_mma(T_N, H_DIM, 3 * DG, 2, DG,
                obj512, DG, pred512, DG, rels, nullptr, 0,
                tWs1a + (size_t)i * H_DIM * 3 * DG, bs1a + (size_t)i * H_DIM,
                hbuf, H_DIM);
        run_mma(T_N, 1536, H_DIM, 0, 0,
                hbuf, H_DIM, nullptr, 0, nullptr, nullptr, 0,
                tWs1b + (size_t)i * 1536 * H_DIM, bs1b + (size_t)i * 1536,
                tbuf, 1536, pred_dst, 512, 1024);
        pool_gather_kernel<<<O_N, 256>>>(tbuf, entries, off, finv, pooled);
        run_mma(O_N, H_DIM, H_DIM, 0, 0, pooled, 512, nullptr, 0, nullptr, nullptr, 0,
                tWs2a + (size_t)i * H_DIM * H_DIM, bs2a + (size_t)i * H_DIM,
                hbuf, H_DIM);
        run_mma(O_N, DG, H_DIM, 0, 0, hbuf, 512, nullptr, 0, nullptr, nullptr, 0,
                tWs2b + (size_t)i * DG * H_DIM, bs2b + (size_t)i * DG,
                obj_dst, DG);
    }
}

// round 7
// speedup vs baseline: 2.9006x; 1.1854x over previous
#include <cuda_runtime.h>
#include <cuda_bf16.h>
#include <cstdint>

typedef __nv_bfloat16 bf16;

#define O_N 2000
#define T_N 6000
#define DIN 2048
#define DW 300
#define DWP 320          // padded table width
#define DG 512
#define H_DIM 512
#define L_EXTRA 4
#define E_N (2*T_N)
#define KP_EMB 2368      // DIN + DWP

#define BM 128
#define BN 128
#define BKC 64           // k per chunk (bf16 elements)
#define ASTR 144         // 64*2 + 16 pad bytes per row
#define TILE_B (128*ASTR)        // 18432
#define STAGE_B (4*TILE_B)       // 73728 (Ah, Al, Bh, Bl)
#define SM_TOTAL (2*STAGE_B)     // 147456

// ---------------- scratch (device globals) ----------------
__device__ __align__(16) bf16 g_eobj_h[O_N*DIN],  g_eobj_l[O_N*DIN];
__device__ __align__(16) bf16 g_epred_h[T_N*DIN], g_epred_l[T_N*DIN];
__device__ __align__(16) bf16 g_tobj_h[1000*DWP], g_tobj_l[1000*DWP];
__device__ __align__(16) bf16 g_trel_h[500*DWP],  g_trel_l[500*DWP];
__device__ __align__(16) bf16 g_objA_h[O_N*DIN],  g_objA_l[O_N*DIN];
__device__ __align__(16) bf16 g_pA_h[T_N*DIN],    g_pA_l[T_N*DIN];
__device__ __align__(16) bf16 g_h_h[T_N*512],     g_h_l[T_N*512];
__device__ __align__(16) bf16 g_p512_h[T_N*512],  g_p512_l[T_N*512];
__device__ __align__(16) bf16 g_pool_h[O_N*512],  g_pool_l[O_N*512];
__device__ __align__(16) bf16 g_o512_h[O_N*512],  g_o512_l[O_N*512];
#define WT_POOL 22544384
__device__ __align__(16) bf16 g_wt_h[WT_POOL], g_wt_l[WT_POOL];
__device__ __align__(16) float g_t[T_N * 1536];
__device__ int   g_cnt[O_N];
__device__ float g_inv[O_N];
__device__ int   g_off[O_N + 1];
__device__ int   g_objarr[E_N];
__device__ int   g_entries[E_N];

// ---------------- PTX helpers ----------------
__device__ __forceinline__ uint32_t smem_u32(const void* p) {
    uint32_t a;
    asm("{ .reg .u64 t; cvta.to.shared.u64 t, %1; cvt.u32.u64 %0, t; }" : "=r"(a) : "l"(p));
    return a;
}
__device__ __forceinline__ void cpa16(uint32_t dst, const void* src, uint32_t sz) {
    asm volatile("cp.async.cg.shared.global [%0], [%1], 16, %2;"
        :: "r"(dst), "l"(src), "r"(sz) : "memory");
}
__device__ __forceinline__ void cpa_commit() {
    asm volatile("cp.async.commit_group;" ::: "memory");
}
template<int N>
__device__ __forceinline__ void cpa_wait() {
    asm volatile("cp.async.wait_group %0;" :: "n"(N) : "memory");
}
__device__ __forceinline__ void ldsm4(uint32_t* r, uint32_t addr) {
    asm volatile("ldmatrix.sync.aligned.m8n8.x4.shared.b16 {%0,%1,%2,%3}, [%4];"
        : "=r"(r[0]), "=r"(r[1]), "=r"(r[2]), "=r"(r[3]) : "r"(addr));
}
__device__ __forceinline__ void mma16816(float* d, const uint32_t* a, const uint32_t* b) {
    asm volatile("mma.sync.aligned.m16n8k16.row.col.f32.bf16.bf16.f32 "
        "{%0,%1,%2,%3}, {%4,%5,%6,%7}, {%8,%9}, {%0,%1,%2,%3};"
        : "+f"(d[0]), "+f"(d[1]), "+f"(d[2]), "+f"(d[3])
        : "r"(a[0]), "r"(a[1]), "r"(a[2]), "r"(a[3]), "r"(b[0]), "r"(b[1]));
}
__device__ __forceinline__ void split1(float v, bf16& h, bf16& l) {
    h = __float2bfloat16_rn(v);
    l = __float2bfloat16_rn(v - __bfloat162float(h));
}

// ---------------- bf16x3 pipelined GEMM ----------------
// C = relu(gather(A) @ Bt^T + bias), A pre-split hi/lo bf16, Bt [Ntot,KP] hi/lo bf16
// mode 0: row = A0[row]
// mode 1: row = [A0[row] (seg) | A1[gidx[row*gstride]] (lda1)]
// mode 2: row = [A0[rels[3r]] | A1[row] | A0[rels[3r+2]]] (each seg wide)
__global__ __launch_bounds__(256, 1)
void mma_gemm_kernel(int M, int KP, int mode, int seg,
                     const bf16* __restrict__ A0h, const bf16* __restrict__ A0l, int lda0,
                     const bf16* __restrict__ A1h, const bf16* __restrict__ A1l, int lda1,
                     const int* __restrict__ rels,
                     const int* __restrict__ gidx, int gstride,
                     const bf16* __restrict__ Bh, const bf16* __restrict__ Bl,
                     const float* __restrict__ bias,
                     float* __restrict__ Cf, bf16* __restrict__ Ch, bf16* __restrict__ Cl, int ldc,
                     float* __restrict__ auxf, bf16* __restrict__ auxh, bf16* __restrict__ auxl,
                     int aux_lo, int aux_hi)
{
    extern __shared__ char smem[];
    const uint32_t sb = smem_u32(smem);
    const int tid = threadIdx.x;
    const int lane = tid & 31;
    const int wid = tid >> 5;
    const int bm = blockIdx.y * BM;
    const int bn = blockIdx.x * BN;

    // loader geometry: 8 colsegs x 32 rows, 4 row-waves
    const int c = tid & 7;
    const int rl = tid >> 3;
    int ia0[4], ia1[4], ia2[4], rB[4];
    uint32_t asz[4];
    #pragma unroll
    for (int i = 0; i < 4; i++) {
        int arow = bm + rl + 32 * i;
        bool v = arow < M;
        asz[i] = v ? 16u : 0u;
        ia0[i] = ia1[i] = ia2[i] = 0;
        if (v) {
            if (mode == 2) {
                ia0[i] = rels[3 * arow];
                ia1[i] = arow;
                ia2[i] = rels[3 * arow + 2];
            } else if (mode == 1) {
                ia0[i] = arow;
                ia1[i] = gidx[(size_t)arow * gstride];
            } else {
                ia0[i] = arow;
            }
        }
        rB[i] = bn + rl + 32 * i;
    }

    float acc[4][4][4];
    #pragma unroll
    for (int a = 0; a < 4; a++)
        #pragma unroll
        for (int b = 0; b < 4; b++)
            #pragma unroll
            for (int d = 0; d < 4; d++) acc[a][b][d] = 0.f;

    const int wr = wid & 1;
    const int wc = wid >> 1;
    const uint32_t a_l_off = (uint32_t)((lane & 15) * ASTR + (lane >> 4) * 16);
    const uint32_t b_l_off = (uint32_t)((((lane & 7) + ((lane >> 4) << 3)) * ASTR) + (((lane >> 3) & 1) << 4));

    const int NT = KP / BKC;

    // ---- chunk issue helper (inlined via lambda-style macro) ----
    auto issue = [&](int it) {
        const int s = it & 1;
        const uint32_t st = sb + (uint32_t)s * STAGE_B;
        const int k0 = it * BKC;
        int segid = 0, koff = k0;
        const bf16 *sh = A0h, *sl = A0l; int ldx = lda0;
        if (mode == 1) {
            if (k0 >= seg) { segid = 1; koff = k0 - seg; sh = A1h; sl = A1l; ldx = lda1; }
        } else if (mode == 2) {
            if (k0 >= 2 * seg)      { segid = 2; koff = k0 - 2 * seg; }
            else if (k0 >= seg)     { segid = 1; koff = k0 - seg; sh = A1h; sl = A1l; ldx = lda1; }
        }
        #pragma unroll
        for (int i = 0; i < 4; i++) {
            int idx = (segid == 0) ? ia0[i] : (segid == 1) ? ia1[i] : ia2[i];
            size_t so = (size_t)idx * ldx + koff + c * 8;
            uint32_t d = st + (uint32_t)((rl + 32 * i) * ASTR + c * 16);
            cpa16(d,          sh + so, asz[i]);
            cpa16(d + TILE_B, sl + so, asz[i]);
        }
        #pragma unroll
        for (int i = 0; i < 4; i++) {
            size_t so = (size_t)rB[i] * KP + k0 + c * 8;
            uint32_t d = st + 2 * TILE_B + (uint32_t)((rl + 32 * i) * ASTR + c * 16);
            cpa16(d,          Bh + so, 16u);
            cpa16(d + TILE_B, Bl + so, 16u);
        }
        cpa_commit();
    };

    issue(0);

    for (int it = 0; it < NT; it++) {
        if (it + 1 < NT) { issue(it + 1); cpa_wait<1>(); }
        else             { cpa_wait<0>(); }
        __syncthreads();

        const uint32_t st = sb + (uint32_t)(it & 1) * STAGE_B;
        const uint32_t aH = st + (uint32_t)(wr * 64 * ASTR) + a_l_off;
        const uint32_t aL = aH + TILE_B;
        const uint32_t bH = st + 2 * TILE_B + (uint32_t)(wc * 32 * ASTR) + b_l_off;
        const uint32_t bL = bH + TILE_B;

        #pragma unroll
        for (int ks = 0; ks < 4; ks++) {
            const uint32_t kb = ks * 32;
            uint32_t af[4][4], bh2[2][4];
            #pragma unroll
            for (int mt = 0; mt < 4; mt++) ldsm4(af[mt], aH + (uint32_t)(mt * 16 * ASTR) + kb);
            #pragma unroll
            for (int np = 0; np < 2; np++) ldsm4(bh2[np], bH + (uint32_t)(np * 16 * ASTR) + kb);
            #pragma unroll
            for (int mt = 0; mt < 4; mt++)
                #pragma unroll
                for (int np = 0; np < 2; np++) {
                    mma16816(acc[mt][2 * np],     af[mt], &bh2[np][0]);
                    mma16816(acc[mt][2 * np + 1], af[mt], &bh2[np][2]);
                }
            uint32_t bl2[2][4];
            #pragma unroll
            for (int np = 0; np < 2; np++) ldsm4(bl2[np], bL + (uint32_t)(np * 16 * ASTR) + kb);
            #pragma unroll
            for (int mt = 0; mt < 4; mt++)
                #pragma unroll
                for (int np = 0; np < 2; np++) {
                    mma16816(acc[mt][2 * np],     af[mt], &bl2[np][0]);
                    mma16816(acc[mt][2 * np + 1], af[mt], &bl2[np][2]);
                }
            #pragma unroll
            for (int mt = 0; mt < 4; mt++) ldsm4(af[mt], aL + (uint32_t)(mt * 16 * ASTR) + kb);
            #pragma unroll
            for (int mt = 0; mt < 4; mt++)
                #pragma unroll
                for (int np = 0; np < 2; np++) {
                    mma16816(acc[mt][2 * np],     af[mt], &bh2[np][0]);
                    mma16816(acc[mt][2 * np + 1], af[mt], &bh2[np][2]);
                }
        }
        __syncthreads();
    }

    // ---- epilogue: bias + relu; fp32 / bf16-split stores ----
    const int g = lane >> 2, qr = lane & 3;
    const int awidth = aux_hi - aux_lo;
    #pragma unroll
    for (int nt = 0; nt < 4; nt++) {
        const int col = bn + wc * 32 + nt * 8 + qr * 2;
        const float2 bv = *reinterpret_cast<const float2*>(bias + col);
        const bool in_aux = (col >= aux_lo) && (col < aux_hi);
        #pragma unroll
        for (int mt = 0; mt < 4; mt++) {
            const int row0 = bm + wr * 64 + mt * 16 + g;
            #pragma unroll
            for (int hh = 0; hh < 2; hh++) {
                const int row = row0 + 8 * hh;
                if (row >= M) continue;
                float v0 = fmaxf(acc[mt][nt][2 * hh]     + bv.x, 0.f);
                float v1 = fmaxf(acc[mt][nt][2 * hh + 1] + bv.y, 0.f);
                if (Cf)
                    *reinterpret_cast<float2*>(Cf + (size_t)row * ldc + col) = make_float2(v0, v1);
                if (Ch) {
                    bf16 h0, l0, h1, l1;
                    split1(v0, h0, l0); split1(v1, h1, l1);
                    __nv_bfloat162 ph; ph.x = h0; ph.y = h1;
                    __nv_bfloat162 pl; pl.x = l0; pl.y = l1;
                    *reinterpret_cast<__nv_bfloat162*>(Ch + (size_t)row * ldc + col) = ph;
                    *reinterpret_cast<__nv_bfloat162*>(Cl + (size_t)row * ldc + col) = pl;
                }
                if (in_aux) {
                    const int ac = col - aux_lo;
                    if (auxf)
                        *reinterpret_cast<float2*>(auxf + (size_t)row * awidth + ac) = make_float2(v0, v1);
                    if (auxh) {
                        bf16 h0, l0, h1, l1;
                        split1(v0, h0, l0); split1(v1, h1, l1);
                        __nv_bfloat162 ph; ph.x = h0; ph.y = h1;
                        __nv_bfloat162 pl; pl.x = l0; pl.y = l1;
                        *reinterpret_cast<__nv_bfloat162*>(auxh + (size_t)row * awidth + ac) = ph;
                        *reinterpret_cast<__nv_bfloat162*>(auxl + (size_t)row * awidth + ac) = pl;
                    }
                }
            }
        }
    }
}

// ---------------- prep kernels ----------------
__global__ void split_kernel(const float* __restrict__ x, int n,
                             bf16* __restrict__ h, bf16* __restrict__ l) {
    int i = blockIdx.x * blockDim.x + threadIdx.x;
    if (i >= n) return;
    float v = x[i];
    bf16 hh, ll; split1(v, hh, ll);
    h[i] = hh; l[i] = ll;
}
__global__ void split_pad_kernel(const float* __restrict__ x, int V, int W, int WP,
                                 bf16* __restrict__ h, bf16* __restrict__ l) {
    int v = blockIdx.x;
    for (int c = threadIdx.x; c < WP; c += blockDim.x) {
        float val = (c < W) ? x[(size_t)v * W + c] : 0.f;
        bf16 hh, ll; split1(val, hh, ll);
        h[(size_t)v * WP + c] = hh;
        l[(size_t)v * WP + c] = ll;
    }
}
// transpose + split: in B[k*N+n] fp32 -> Bth/Btl[n*KP+k] bf16 (zero for k>=K)
__global__ void tsplit_kernel(const float* __restrict__ B, bf16* __restrict__ Bth,
                              bf16* __restrict__ Btl, int K, int N, int KP) {
    __shared__ float tile[32][33];
    int bk = blockIdx.x * 32, bn = blockIdx.y * 32;
    int x = threadIdx.x, y = threadIdx.y;
    for (int i = y; i < 32; i += 8) {
        int k = bk + i, n = bn + x;
        tile[i][x] = (k < K && n < N) ? B[(size_t)k * N + n] : 0.f;
    }
    __syncthreads();
    for (int i = y; i < 32; i += 8) {
        int n = bn + i, k = bk + x;
        if (n < N && k < KP) {
            float v = tile[x][i];
            bf16 hh, ll; split1(v, hh, ll);
            Bth[(size_t)n * KP + k] = hh;
            Btl[(size_t)n * KP + k] = ll;
        }
    }
}

// ---------------- deterministic scatter-mean pooling ----------------
__global__ void zero_int_kernel(int* p, int n) {
    int i = blockIdx.x * blockDim.x + threadIdx.x;
    if (i < n) p[i] = 0;
}
__global__ void build_count_kernel(const int* __restrict__ rels, int* __restrict__ objarr,
                                   int* __restrict__ cnt) {
    int e = blockIdx.x * blockDim.x + threadIdx.x;
    if (e >= E_N) return;
    int t = e >> 1;
    int v = rels[3 * t + ((e & 1) ? 2 : 0)];
    objarr[e] = v;
    atomicAdd(&cnt[v], 1);
}
__global__ void scan_kernel(const int* __restrict__ cnt, int* __restrict__ off,
                            float* __restrict__ inv) {
    __shared__ int buf[2][2048];
    int tid = threadIdx.x;
    for (int i = tid; i < 2048; i += 1024) {
        int c = (i < O_N) ? cnt[i] : 0;
        buf[0][i] = c;
        if (i < O_N) inv[i] = 1.0f / fmaxf((float)c, 1.0f);
    }
    __syncthreads();
    int src = 0;
    for (int d = 1; d < 2048; d <<= 1) {
        for (int i = tid; i < 2048; i += 1024) {
            int v = buf[src][i];
            if (i >= d) v += buf[src][i - d];
            buf[1 - src][i] = v;
        }
        src = 1 - src;
        __syncthreads();
    }
    for (int i = tid; i < O_N; i += 1024) off[i] = (i == 0) ? 0 : buf[src][i - 1];
    if (tid == 0) off[O_N] = buf[src][O_N - 1];
}
__global__ void rank_fill_kernel(const int* __restrict__ objarr, const int* __restrict__ off,
                                 int* __restrict__ entries) {
    int i = blockIdx.x * blockDim.x + threadIdx.x;
    if (i >= O_N) return;
    int w = off[i];
    for (int e = 0; e < E_N; e++)
        if (objarr[e] == i) entries[w++] = e;
}
// pooled (mean) -> split bf16 hi/lo
__global__ void pool_gather_kernel(const float* __restrict__ t,
                                   const int* __restrict__ entries, const int* __restrict__ off,
                                   const float* __restrict__ inv,
                                   bf16* __restrict__ ph, bf16* __restrict__ pl) {
    int i = blockIdx.x;
    int c0 = threadIdx.x;
    int beg = off[i], end = off[i + 1];
    float s0 = 0.f, s1 = 0.f;
    for (int p = beg; p < end; p++) {
        int e = entries[p];
        int tr = e >> 1;
        const float* src = t + (size_t)tr * 1536 + ((e & 1) ? 1024 : 0);
        s0 += src[c0];
        s1 += src[c0 + 256];
    }
    float iv = inv[i];
    float v0 = s0 * iv, v1 = s1 * iv;
    bf16 h, l;
    split1(v0, h, l);
    ph[(size_t)i * 512 + c0] = h; pl[(size_t)i * 512 + c0] = l;
    split1(v1, h, l);
    ph[(size_t)i * 512 + c0 + 256] = h; pl[(size_t)i * 512 + c0 + 256] = l;
}

// ---------------- host glue ----------------
struct GPtr { bf16 *h, *l; };

static inline void run_mma(int M, int Ntot, int KP, int mode, int seg,
                           GPtr A0, int lda0, GPtr A1, int lda1,
                           const int* rels, const int* gidx, int gstride,
                           GPtr Bt, const float* bias,
                           float* Cf, GPtr C, int ldc,
                           float* auxf = nullptr, GPtr aux = {nullptr, nullptr},
                           int aux_lo = 0, int aux_hi = 0)
{
    dim3 grid(Ntot / BN, (M + BM - 1) / BM);
    mma_gemm_kernel<<<grid, 256, SM_TOTAL>>>(M, KP, mode, seg,
        A0.h, A0.l, lda0, A1.h, A1.l, lda1, rels, gidx, gstride,
        Bt.h, Bt.l, bias, Cf, C.h, C.l, ldc, auxf, aux.h, aux.l, aux_lo, aux_hi);
}

extern "C" void kernel_launch(void* const* d_in, const int* in_sizes, int n_in,
                              void* d_out, int out_size)
{
    const float* obj_embs  = (const float*)d_in[0];
    const float* pred_embs = (const float*)d_in[2];
    const int*   rels      = (const int*)d_in[4];
    const int*   objs      = (const int*)d_in[5];
    const float* obj_table = (const float*)d_in[6];
    const float* rel_table = (const float*)d_in[7];
    const float* Wf_obj    = (const float*)d_in[8];
    const float* bf_obj    = (const float*)d_in[9];
    const float* Wf_rel    = (const float*)d_in[10];
    const float* bf_rel    = (const float*)d_in[11];
    const float* W1a       = (const float*)d_in[12];
    const float* b1a       = (const float*)d_in[13];
    const float* W1b       = (const float*)d_in[14];
    const float* b1b       = (const float*)d_in[15];
    const float* W2a       = (const float*)d_in[16];
    const float* b2a       = (const float*)d_in[17];
    const float* W2b       = (const float*)d_in[18];
    const float* b2b       = (const float*)d_in[19];
    const float* Ws1a      = (const float*)d_in[20];
    const float* bs1a      = (const float*)d_in[21];
    const float* Ws1b      = (const float*)d_in[22];
    const float* bs1b      = (const float*)d_in[23];
    const float* Ws2a      = (const float*)d_in[24];
    const float* bs2a      = (const float*)d_in[25];
    const float* Ws2b      = (const float*)d_in[26];
    const float* bs2b      = (const float*)d_in[27];
    float* out = (float*)d_out;

    cudaFuncSetAttribute(mma_gemm_kernel, cudaFuncAttributeMaxDynamicSharedMemorySize, SM_TOTAL);

    auto sym = [](const void* s) { void* p; cudaGetSymbolAddress(&p, s); return p; };
    GPtr eobj  = {(bf16*)sym(g_eobj_h),  (bf16*)sym(g_eobj_l)};
    GPtr epred = {(bf16*)sym(g_epred_h), (bf16*)sym(g_epred_l)};
    GPtr tobj  = {(bf16*)sym(g_tobj_h),  (bf16*)sym(g_tobj_l)};
    GPtr trel  = {(bf16*)sym(g_trel_h),  (bf16*)sym(g_trel_l)};
    GPtr objA  = {(bf16*)sym(g_objA_h),  (bf16*)sym(g_objA_l)};
    GPtr pA    = {(bf16*)sym(g_pA_h),    (bf16*)sym(g_pA_l)};
    GPtr hb    = {(bf16*)sym(g_h_h),     (bf16*)sym(g_h_l)};
    GPtr p512  = {(bf16*)sym(g_p512_h),  (bf16*)sym(g_p512_l)};
    GPtr pool  = {(bf16*)sym(g_pool_h),  (bf16*)sym(g_pool_l)};
    GPtr o512  = {(bf16*)sym(g_o512_h),  (bf16*)sym(g_o512_l)};
    bf16* wth = (bf16*)sym(g_wt_h);
    bf16* wtl = (bf16*)sym(g_wt_l);
    float* tbuf = (float*)sym(g_t);
    int* cnt = (int*)sym(g_cnt);
    int* off = (int*)sym(g_off);
    int* objarr = (int*)sym(g_objarr);
    int* entries = (int*)sym(g_entries);
    float* finv = (float*)sym(g_inv);

    // weight pool offsets (bf16 elems)
    size_t po = 0;
    auto take = [&](size_t n) { GPtr r = {wth + po, wtl + po}; po += n; return r; };
    GPtr tWfobj = take((size_t)DIN * KP_EMB);
    GPtr tWfrel = take((size_t)DIN * KP_EMB);
    GPtr tW1a   = take((size_t)H_DIM * 3 * DIN);
    GPtr tW1b   = take((size_t)1536 * H_DIM);
    GPtr tW2a   = take((size_t)H_DIM * H_DIM);
    GPtr tW2b   = take((size_t)DG * H_DIM);
    GPtr tWs1a  = take((size_t)L_EXTRA * H_DIM * 3 * DG);
    GPtr tWs1b  = take((size_t)L_EXTRA * 1536 * H_DIM);
    GPtr tWs2a  = take((size_t)L_EXTRA * H_DIM * H_DIM);
    GPtr tWs2b  = take((size_t)L_EXTRA * DG * H_DIM);

    auto ts = [](const float* B, GPtr Bt, int K, int N, int KP) {
        dim3 grid((KP + 31) / 32, (N + 31) / 32);
        tsplit_kernel<<<grid, dim3(32, 8)>>>(B, Bt.h, Bt.l, K, N, KP);
    };

    // --- prep: splits + transposes ---
    split_kernel<<<(O_N * DIN + 255) / 256, 256>>>(obj_embs, O_N * DIN, eobj.h, eobj.l);
    split_kernel<<<(T_N * DIN + 255) / 256, 256>>>(pred_embs, T_N * DIN, epred.h, epred.l);
    split_pad_kernel<<<1000, 256>>>(obj_table, 1000, DW, DWP, tobj.h, tobj.l);
    split_pad_kernel<<<500, 256>>>(rel_table, 500, DW, DWP, trel.h, trel.l);

    ts(Wf_obj, tWfobj, DIN + DW, DIN, KP_EMB);
    ts(Wf_rel, tWfrel, DIN + DW, DIN, KP_EMB);
    ts(W1a, tW1a, 3 * DIN, H_DIM, 3 * DIN);
    ts(W1b, tW1b, H_DIM, 1536, H_DIM);
    ts(W2a, tW2a, H_DIM, H_DIM, H_DIM);
    ts(W2b, tW2b, H_DIM, DG, H_DIM);
    for (int i = 0; i < L_EXTRA; i++) {
        ts(Ws1a + (size_t)i * 3 * DG * H_DIM, {tWs1a.h + (size_t)i * H_DIM * 3 * DG, tWs1a.l + (size_t)i * H_DIM * 3 * DG}, 3 * DG, H_DIM, 3 * DG);
        ts(Ws1b + (size_t)i * H_DIM * 1536,   {tWs1b.h + (size_t)i * 1536 * H_DIM,   tWs1b.l + (size_t)i * 1536 * H_DIM},   H_DIM, 1536, H_DIM);
        ts(Ws2a + (size_t)i * H_DIM * H_DIM,  {tWs2a.h + (size_t)i * H_DIM * H_DIM,  tWs2a.l + (size_t)i * H_DIM * H_DIM},  H_DIM, H_DIM, H_DIM);
        ts(Ws2b + (size_t)i * H_DIM * DG,     {tWs2b.h + (size_t)i * DG * H_DIM,     tWs2b.l + (size_t)i * DG * H_DIM},     H_DIM, DG, H_DIM);
    }

    // --- CSR for deterministic pooling ---
    zero_int_kernel<<<(O_N + 255) / 256, 256>>>(cnt, O_N);
    build_count_kernel<<<(E_N + 255) / 256, 256>>>(rels, objarr, cnt);
    scan_kernel<<<1, 1024>>>(cnt, off, finv);
    rank_fill_kernel<<<(O_N + 255) / 256, 256>>>(objarr, off, entries);

    GPtr nullg = {nullptr, nullptr};

    // --- embedding GEMMs ---
    run_mma(O_N, DIN, KP_EMB, 1, DIN, eobj, DIN, tobj, DWP, nullptr, objs, 1,
            tWfobj, bf_obj, nullptr, objA, DIN);
    run_mma(T_N, DIN, KP_EMB, 1, DIN, epred, DIN, trel, DWP, nullptr, rels + 1, 3,
            tWfrel, bf_rel, nullptr, pA, DIN);

    // --- layer 0 ---
    run_mma(T_N, H_DIM, 3 * DIN, 2, DIN, objA, DIN, pA, DIN, rels, nullptr, 0,
            tW1a, b1a, nullptr, hb, H_DIM);
    run_mma(T_N, 1536, H_DIM, 0, 0, hb, H_DIM, nullg, 0, nullptr, nullptr, 0,
            tW1b, b1b, tbuf, nullg, 1536, nullptr, p512, 512, 1024);
    pool_gather_kernel<<<O_N, 256>>>(tbuf, entries, off, finv, pool.h, pool.l);
    run_mma(O_N, H_DIM, H_DIM, 0, 0, pool, 512, nullg, 0, nullptr, nullptr, 0,
            tW2a, b2a, nullptr, hb, H_DIM);
    run_mma(O_N, DG, H_DIM, 0, 0, hb, 512, nullg, 0, nullptr, nullptr, 0,
            tW2b, b2b, nullptr, o512, DG);

    // --- extra layers ---
    for (int i = 0; i < L_EXTRA; i++) {
        const bool last = (i == L_EXTRA - 1);
        GPtr w1a = {tWs1a.h + (size_t)i * H_DIM * 3 * DG, tWs1a.l + (size_t)i * H_DIM * 3 * DG};
        GPtr w1b = {tWs1b.h + (size_t)i * 1536 * H_DIM,   tWs1b.l + (size_t)i * 1536 * H_DIM};
        GPtr w2a = {tWs2a.h + (size_t)i * H_DIM * H_DIM,  tWs2a.l + (size_t)i * H_DIM * H_DIM};
        GPtr w2b = {tWs2b.h + (size_t)i * DG * H_DIM,     tWs2b.l + (size_t)i * DG * H_DIM};

        run_mma(T_N, H_DIM, 3 * DG, 2, DG, o512, DG, p512, DG, rels, nullptr, 0,
                w1a, bs1a + (size_t)i * H_DIM, nullptr, hb, H_DIM);
        run_mma(T_N, 1536, H_DIM, 0, 0, hb, H_DIM, nullg, 0, nullptr, nullptr, 0,
                w1b, bs1b + (size_t)i * 1536, tbuf, nullg, 1536,
                last ? (out + (size_t)O_N * DG) : nullptr,
                last ? nullg : p512, 512, 1024);
        pool_gather_kernel<<<O_N, 256>>>(tbuf, entries, off, finv, pool.h, pool.l);
        run_mma(O_N, H_DIM, H_DIM, 0, 0, pool, 512, nullg, 0, nullptr, nullptr, 0,
                w2a, bs2a + (size_t)i * H_DIM, nullptr, hb, H_DIM);
        run_mma(O_N, DG, H_DIM, 0, 0, hb, 512, nullg, 0, nullptr, nullptr, 0,
                w2b, bs2b + (size_t)i * DG,
                last ? out : nullptr, last ? nullg : o512, DG);
    }
}

// round 8
// speedup vs baseline: 3.0894x; 1.0651x over previous
#include <cuda_runtime.h>
#include <cuda_bf16.h>
#include <cstdint>

typedef __nv_bfloat16 bf16;

#define O_N 2000
#define T_N 6000
#define DIN 2048
#define DW 300
#define DWP 320          // padded table width
#define DG 512
#define H_DIM 512
#define L_EXTRA 4
#define E_N (2*T_N)
#define KP_EMB 2368      // DIN + DWP

#define BN 128
#define BKC 64           // k per chunk (bf16 elements)
#define ASTR 144         // 64*2 + 16 pad bytes per row

// ---------------- scratch (device globals) ----------------
__device__ __align__(16) bf16 g_eobj_h[O_N*DIN],  g_eobj_l[O_N*DIN];
__device__ __align__(16) bf16 g_epred_h[T_N*DIN], g_epred_l[T_N*DIN];
__device__ __align__(16) bf16 g_tobj_h[1000*DWP], g_tobj_l[1000*DWP];
__device__ __align__(16) bf16 g_trel_h[500*DWP],  g_trel_l[500*DWP];
__device__ __align__(16) bf16 g_objA_h[O_N*DIN],  g_objA_l[O_N*DIN];
__device__ __align__(16) bf16 g_pA_h[T_N*DIN],    g_pA_l[T_N*DIN];
__device__ __align__(16) bf16 g_h_h[T_N*512],     g_h_l[T_N*512];
__device__ __align__(16) bf16 g_p512_h[T_N*512],  g_p512_l[T_N*512];
__device__ __align__(16) bf16 g_pool_h[O_N*512],  g_pool_l[O_N*512];
__device__ __align__(16) bf16 g_o512_h[O_N*512],  g_o512_l[O_N*512];
#define WT_POOL 22544384
__device__ __align__(16) bf16 g_wt_h[WT_POOL], g_wt_l[WT_POOL];
__device__ __align__(16) float g_t[T_N * 1536];
__device__ int   g_cnt[O_N];
__device__ float g_inv[O_N];
__device__ int   g_off[O_N + 1];
__device__ int   g_objarr[E_N];
__device__ int   g_entries[E_N];

// ---------------- PTX helpers ----------------
__device__ __forceinline__ uint32_t smem_u32(const void* p) {
    uint32_t a;
    asm("{ .reg .u64 t; cvta.to.shared.u64 t, %1; cvt.u32.u64 %0, t; }" : "=r"(a) : "l"(p));
    return a;
}
__device__ __forceinline__ void cpa16(uint32_t dst, const void* src, uint32_t sz) {
    asm volatile("cp.async.cg.shared.global [%0], [%1], 16, %2;"
        :: "r"(dst), "l"(src), "r"(sz) : "memory");
}
__device__ __forceinline__ void cpa_commit() {
    asm volatile("cp.async.commit_group;" ::: "memory");
}
template<int N>
__device__ __forceinline__ void cpa_wait() {
    asm volatile("cp.async.wait_group %0;" :: "n"(N) : "memory");
}
__device__ __forceinline__ void ldsm4(uint32_t* r, uint32_t addr) {
    asm volatile("ldmatrix.sync.aligned.m8n8.x4.shared.b16 {%0,%1,%2,%3}, [%4];"
        : "=r"(r[0]), "=r"(r[1]), "=r"(r[2]), "=r"(r[3]) : "r"(addr));
}
__device__ __forceinline__ void mma16816(float* d, const uint32_t* a, const uint32_t* b) {
    asm volatile("mma.sync.aligned.m16n8k16.row.col.f32.bf16.bf16.f32 "
        "{%0,%1,%2,%3}, {%4,%5,%6,%7}, {%8,%9}, {%0,%1,%2,%3};"
        : "+f"(d[0]), "+f"(d[1]), "+f"(d[2]), "+f"(d[3])
        : "r"(a[0]), "r"(a[1]), "r"(a[2]), "r"(a[3]), "r"(b[0]), "r"(b[1]));
}
__device__ __forceinline__ void split1(float v, bf16& h, bf16& l) {
    h = __float2bfloat16_rn(v);
    l = __float2bfloat16_rn(v - __bfloat162float(h));
}

// ---------------- bf16x3 pipelined GEMM, templated on MT (m16 tiles per warp) ----------------
// BM = 32*MT. MT=4 -> 128x128 tile (1 CTA/SM); MT=2 -> 64x128 tile (2 CTA/SM).
// C = relu(gather(A) @ Bt^T + bias)
// mode 0: row = A0[row]
// mode 1: row = [A0[row] (seg) | A1[gidx[row*gstride]]]
// mode 2: row = [A0[rels[3r]] | A1[row] | A0[rels[3r+2]]] (each seg wide)
template<int MT>
__global__ __launch_bounds__(256, (MT == 2 ? 2 : 1))
void mma_gemm_kernel(int M, int KP, int mode, int seg,
                     const bf16* __restrict__ A0h, const bf16* __restrict__ A0l, int lda0,
                     const bf16* __restrict__ A1h, const bf16* __restrict__ A1l, int lda1,
                     const int* __restrict__ rels,
                     const int* __restrict__ gidx, int gstride,
                     const bf16* __restrict__ Bh, const bf16* __restrict__ Bl,
                     const float* __restrict__ bias,
                     float* __restrict__ Cf, bf16* __restrict__ Ch, bf16* __restrict__ Cl, int ldc,
                     float* __restrict__ auxf, bf16* __restrict__ auxh, bf16* __restrict__ auxl,
                     int aux_lo, int aux_hi)
{
    constexpr int BM = 32 * MT;
    constexpr int ATILE = BM * ASTR;         // bytes, one A (h or l) tile
    constexpr int BTILE = 128 * ASTR;
    constexpr int STAGE = 2 * ATILE + 2 * BTILE;

    extern __shared__ char smem[];
    const uint32_t sb = smem_u32(smem);
    const int tid = threadIdx.x;
    const int lane = tid & 31;
    const int wid = tid >> 5;
    const int bm = blockIdx.y * BM;
    const int bn = blockIdx.x * BN;

    // loader geometry: 8 colsegs x 32 rows per wave
    const int c = tid & 7;
    const int rl = tid >> 3;
    int ia0[MT], ia1[MT], ia2[MT], rB[4];
    uint32_t asz[MT];
    #pragma unroll
    for (int i = 0; i < MT; i++) {
        int arow = bm + rl + 32 * i;
        bool v = arow < M;
        asz[i] = v ? 16u : 0u;
        ia0[i] = ia1[i] = ia2[i] = 0;
        if (v) {
            if (mode == 2) {
                ia0[i] = rels[3 * arow];
                ia1[i] = arow;
                ia2[i] = rels[3 * arow + 2];
            } else if (mode == 1) {
                ia0[i] = arow;
                ia1[i] = gidx[(size_t)arow * gstride];
            } else {
                ia0[i] = arow;
            }
        }
    }
    #pragma unroll
    for (int i = 0; i < 4; i++) rB[i] = bn + rl + 32 * i;

    float acc[MT][4][4];
    #pragma unroll
    for (int a = 0; a < MT; a++)
        #pragma unroll
        for (int b = 0; b < 4; b++)
            #pragma unroll
            for (int d = 0; d < 4; d++) acc[a][b][d] = 0.f;

    const int wr = wid & 1;
    const int wc = wid >> 1;
    const uint32_t a_l_off = (uint32_t)((lane & 15) * ASTR + (lane >> 4) * 16);
    const uint32_t b_l_off = (uint32_t)((((lane & 7) + ((lane >> 4) << 3)) * ASTR) + (((lane >> 3) & 1) << 4));

    const int NT = KP / BKC;

    auto issue = [&](int it) {
        const int s = it & 1;
        const uint32_t st = sb + (uint32_t)s * STAGE;
        const int k0 = it * BKC;
        int segid = 0, koff = k0;
        const bf16 *sh = A0h, *sl = A0l; int ldx = lda0;
        if (mode == 1) {
            if (k0 >= seg) { segid = 1; koff = k0 - seg; sh = A1h; sl = A1l; ldx = lda1; }
        } else if (mode == 2) {
            if (k0 >= 2 * seg)      { segid = 2; koff = k0 - 2 * seg; }
            else if (k0 >= seg)     { segid = 1; koff = k0 - seg; sh = A1h; sl = A1l; ldx = lda1; }
        }
        #pragma unroll
        for (int i = 0; i < MT; i++) {
            int idx = (segid == 0) ? ia0[i] : (segid == 1) ? ia1[i] : ia2[i];
            size_t so = (size_t)idx * ldx + koff + c * 8;
            uint32_t d = st + (uint32_t)((rl + 32 * i) * ASTR + c * 16);
            cpa16(d,         sh + so, asz[i]);
            cpa16(d + ATILE, sl + so, asz[i]);
        }
        #pragma unroll
        for (int i = 0; i < 4; i++) {
            size_t so = (size_t)rB[i] * KP + k0 + c * 8;
            uint32_t d = st + 2 * ATILE + (uint32_t)((rl + 32 * i) * ASTR + c * 16);
            cpa16(d,         Bh + so, 16u);
            cpa16(d + BTILE, Bl + so, 16u);
        }
        cpa_commit();
    };

    issue(0);

    for (int it = 0; it < NT; it++) {
        if (it + 1 < NT) { issue(it + 1); cpa_wait<1>(); }
        else             { cpa_wait<0>(); }
        __syncthreads();

        const uint32_t st = sb + (uint32_t)(it & 1) * STAGE;
        const uint32_t aH = st + (uint32_t)(wr * 16 * MT * ASTR) + a_l_off;
        const uint32_t aL = aH + ATILE;
        const uint32_t bH = st + 2 * ATILE + (uint32_t)(wc * 32 * ASTR) + b_l_off;
        const uint32_t bL = bH + BTILE;

        #pragma unroll
        for (int ks = 0; ks < 4; ks++) {
            const uint32_t kb = ks * 32;
            uint32_t af[MT][4], bh2[2][4];
            #pragma unroll
            for (int mt = 0; mt < MT; mt++) ldsm4(af[mt], aH + (uint32_t)(mt * 16 * ASTR) + kb);
            #pragma unroll
            for (int np = 0; np < 2; np++) ldsm4(bh2[np], bH + (uint32_t)(np * 16 * ASTR) + kb);
            #pragma unroll
            for (int mt = 0; mt < MT; mt++)
                #pragma unroll
                for (int np = 0; np < 2; np++) {
                    mma16816(acc[mt][2 * np],     af[mt], &bh2[np][0]);
                    mma16816(acc[mt][2 * np + 1], af[mt], &bh2[np][2]);
                }
            uint32_t bl2[2][4];
            #pragma unroll
            for (int np = 0; np < 2; np++) ldsm4(bl2[np], bL + (uint32_t)(np * 16 * ASTR) + kb);
            #pragma unroll
            for (int mt = 0; mt < MT; mt++)
                #pragma unroll
                for (int np = 0; np < 2; np++) {
                    mma16816(acc[mt][2 * np],     af[mt], &bl2[np][0]);
                    mma16816(acc[mt][2 * np + 1], af[mt], &bl2[np][2]);
                }
            #pragma unroll
            for (int mt = 0; mt < MT; mt++) ldsm4(af[mt], aL + (uint32_t)(mt * 16 * ASTR) + kb);
            #pragma unroll
            for (int mt = 0; mt < MT; mt++)
                #pragma unroll
                for (int np = 0; np < 2; np++) {
                    mma16816(acc[mt][2 * np],     af[mt], &bh2[np][0]);
                    mma16816(acc[mt][2 * np + 1], af[mt], &bh2[np][2]);
                }
        }
        __syncthreads();
    }

    // ---- epilogue: bias + relu; fp32 / bf16-split stores ----
    const int g = lane >> 2, qr = lane & 3;
    const int awidth = aux_hi - aux_lo;
    #pragma unroll
    for (int nt = 0; nt < 4; nt++) {
        const int col = bn + wc * 32 + nt * 8 + qr * 2;
        const float2 bv = *reinterpret_cast<const float2*>(bias + col);
        const bool in_aux = (col >= aux_lo) && (col < aux_hi);
        #pragma unroll
        for (int mt = 0; mt < MT; mt++) {
            const int row0 = bm + wr * 16 * MT + mt * 16 + g;
            #pragma unroll
            for (int hh = 0; hh < 2; hh++) {
                const int row = row0 + 8 * hh;
                if (row >= M) continue;
                float v0 = fmaxf(acc[mt][nt][2 * hh]     + bv.x, 0.f);
                float v1 = fmaxf(acc[mt][nt][2 * hh + 1] + bv.y, 0.f);
                if (Cf)
                    *reinterpret_cast<float2*>(Cf + (size_t)row * ldc + col) = make_float2(v0, v1);
                if (Ch) {
                    bf16 h0, l0, h1, l1;
                    split1(v0, h0, l0); split1(v1, h1, l1);
                    __nv_bfloat162 ph; ph.x = h0; ph.y = h1;
                    __nv_bfloat162 pl; pl.x = l0; pl.y = l1;
                    *reinterpret_cast<__nv_bfloat162*>(Ch + (size_t)row * ldc + col) = ph;
                    *reinterpret_cast<__nv_bfloat162*>(Cl + (size_t)row * ldc + col) = pl;
                }
                if (in_aux) {
                    const int ac = col - aux_lo;
                    if (auxf)
                        *reinterpret_cast<float2*>(auxf + (size_t)row * awidth + ac) = make_float2(v0, v1);
                    if (auxh) {
                        bf16 h0, l0, h1, l1;
                        split1(v0, h0, l0); split1(v1, h1, l1);
                        __nv_bfloat162 ph; ph.x = h0; ph.y = h1;
                        __nv_bfloat162 pl; pl.x = l0; pl.y = l1;
                        *reinterpret_cast<__nv_bfloat162*>(auxh + (size_t)row * awidth + ac) = ph;
                        *reinterpret_cast<__nv_bfloat162*>(auxl + (size_t)row * awidth + ac) = pl;
                    }
                }
            }
        }
    }
}

// ---------------- prep kernels ----------------
__global__ void split_kernel(const float* __restrict__ x, int n,
                             bf16* __restrict__ h, bf16* __restrict__ l) {
    int i = blockIdx.x * blockDim.x + threadIdx.x;
    if (i >= n) return;
    float v = x[i];
    bf16 hh, ll; split1(v, hh, ll);
    h[i] = hh; l[i] = ll;
}
__global__ void split_pad_kernel(const float* __restrict__ x, int V, int W, int WP,
                                 bf16* __restrict__ h, bf16* __restrict__ l) {
    int v = blockIdx.x;
    for (int c = threadIdx.x; c < WP; c += blockDim.x) {
        float val = (c < W) ? x[(size_t)v * W + c] : 0.f;
        bf16 hh, ll; split1(val, hh, ll);
        h[(size_t)v * WP + c] = hh;
        l[(size_t)v * WP + c] = ll;
    }
}
__global__ void tsplit_kernel(const float* __restrict__ B, bf16* __restrict__ Bth,
                              bf16* __restrict__ Btl, int K, int N, int KP) {
    __shared__ float tile[32][33];
    int bk = blockIdx.x * 32, bn = blockIdx.y * 32;
    int x = threadIdx.x, y = threadIdx.y;
    for (int i = y; i < 32; i += 8) {
        int k = bk + i, n = bn + x;
        tile[i][x] = (k < K && n < N) ? B[(size_t)k * N + n] : 0.f;
    }
    __syncthreads();
    for (int i = y; i < 32; i += 8) {
        int n = bn + i, k = bk + x;
        if (n < N && k < KP) {
            float v = tile[x][i];
            bf16 hh, ll; split1(v, hh, ll);
            Bth[(size_t)n * KP + k] = hh;
            Btl[(size_t)n * KP + k] = ll;
        }
    }
}

// ---------------- deterministic scatter-mean pooling ----------------
__global__ void zero_int_kernel(int* p, int n) {
    int i = blockIdx.x * blockDim.x + threadIdx.x;
    if (i < n) p[i] = 0;
}
__global__ void build_count_kernel(const int* __restrict__ rels, int* __restrict__ objarr,
                                   int* __restrict__ cnt) {
    int e = blockIdx.x * blockDim.x + threadIdx.x;
    if (e >= E_N) return;
    int t = e >> 1;
    int v = rels[3 * t + ((e & 1) ? 2 : 0)];
    objarr[e] = v;
    atomicAdd(&cnt[v], 1);
}
__global__ void scan_kernel(const int* __restrict__ cnt, int* __restrict__ off,
                            float* __restrict__ inv) {
    __shared__ int buf[2][2048];
    int tid = threadIdx.x;
    for (int i = tid; i < 2048; i += 1024) {
        int c = (i < O_N) ? cnt[i] : 0;
        buf[0][i] = c;
        if (i < O_N) inv[i] = 1.0f / fmaxf((float)c, 1.0f);
    }
    __syncthreads();
    int src = 0;
    for (int d = 1; d < 2048; d <<= 1) {
        for (int i = tid; i < 2048; i += 1024) {
            int v = buf[src][i];
            if (i >= d) v += buf[src][i - d];
            buf[1 - src][i] = v;
        }
        src = 1 - src;
        __syncthreads();
    }
    for (int i = tid; i < O_N; i += 1024) off[i] = (i == 0) ? 0 : buf[src][i - 1];
    if (tid == 0) off[O_N] = buf[src][O_N - 1];
}
__global__ void rank_fill_kernel(const int* __restrict__ objarr, const int* __restrict__ off,
                                 int* __restrict__ entries) {
    int i = blockIdx.x * blockDim.x + threadIdx.x;
    if (i >= O_N) return;
    int w = off[i];
    for (int e = 0; e < E_N; e++)
        if (objarr[e] == i) entries[w++] = e;
}
__global__ void pool_gather_kernel(const float* __restrict__ t,
                                   const int* __restrict__ entries, const int* __restrict__ off,
                                   const float* __restrict__ inv,
                                   bf16* __restrict__ ph, bf16* __restrict__ pl) {
    int i = blockIdx.x;
    int c0 = threadIdx.x;
    int beg = off[i], end = off[i + 1];
    float s0 = 0.f, s1 = 0.f;
    for (int p = beg; p < end; p++) {
        int e = entries[p];
        int tr = e >> 1;
        const float* src = t + (size_t)tr * 1536 + ((e & 1) ? 1024 : 0);
        s0 += src[c0];
        s1 += src[c0 + 256];
    }
    float iv = inv[i];
    float v0 = s0 * iv, v1 = s1 * iv;
    bf16 h, l;
    split1(v0, h, l);
    ph[(size_t)i * 512 + c0] = h; pl[(size_t)i * 512 + c0] = l;
    split1(v1, h, l);
    ph[(size_t)i * 512 + c0 + 256] = h; pl[(size_t)i * 512 + c0 + 256] = l;
}

// ---------------- host glue ----------------
struct GPtr { bf16 *h, *l; };

#define SMEM_MT4 (2 * (2*128*ASTR + 2*128*ASTR))   // 147456
#define SMEM_MT2 (2 * (2*64*ASTR + 2*128*ASTR))    // 110592

static inline void run_mma(int MT, int M, int Ntot, int KP, int mode, int seg,
                           GPtr A0, int lda0, GPtr A1, int lda1,
                           const int* rels, const int* gidx, int gstride,
                           GPtr Bt, const float* bias,
                           float* Cf, GPtr C, int ldc,
                           float* auxf = nullptr, GPtr aux = {nullptr, nullptr},
                           int aux_lo = 0, int aux_hi = 0)
{
    if (MT == 4) {
        dim3 grid(Ntot / BN, (M + 127) / 128);
        mma_gemm_kernel<4><<<grid, 256, SMEM_MT4>>>(M, KP, mode, seg,
            A0.h, A0.l, lda0, A1.h, A1.l, lda1, rels, gidx, gstride,
            Bt.h, Bt.l, bias, Cf, C.h, C.l, ldc, auxf, aux.h, aux.l, aux_lo, aux_hi);
    } else {
        dim3 grid(Ntot / BN, (M + 63) / 64);
        mma_gemm_kernel<2><<<grid, 256, SMEM_MT2>>>(M, KP, mode, seg,
            A0.h, A0.l, lda0, A1.h, A1.l, lda1, rels, gidx, gstride,
            Bt.h, Bt.l, bias, Cf, C.h, C.l, ldc, auxf, aux.h, aux.l, aux_lo, aux_hi);
    }
}

extern "C" void kernel_launch(void* const* d_in, const int* in_sizes, int n_in,
                              void* d_out, int out_size)
{
    const float* obj_embs  = (const float*)d_in[0];
    const float* pred_embs = (const float*)d_in[2];
    const int*   rels      = (const int*)d_in[4];
    const int*   objs      = (const int*)d_in[5];
    const float* obj_table = (const float*)d_in[6];
    const float* rel_table = (const float*)d_in[7];
    const float* Wf_obj    = (const float*)d_in[8];
    const float* bf_obj    = (const float*)d_in[9];
    const float* Wf_rel    = (const float*)d_in[10];
    const float* bf_rel    = (const float*)d_in[11];
    const float* W1a       = (const float*)d_in[12];
    const float* b1a       = (const float*)d_in[13];
    const float* W1b       = (const float*)d_in[14];
    const float* b1b       = (const float*)d_in[15];
    const float* W2a       = (const float*)d_in[16];
    const float* b2a       = (const float*)d_in[17];
    const float* W2b       = (const float*)d_in[18];
    const float* b2b       = (const float*)d_in[19];
    const float* Ws1a      = (const float*)d_in[20];
    const float* bs1a      = (const float*)d_in[21];
    const float* Ws1b      = (const float*)d_in[22];
    const float* bs1b      = (const float*)d_in[23];
    const float* Ws2a      = (const float*)d_in[24];
    const float* bs2a      = (const float*)d_in[25];
    const float* Ws2b      = (const float*)d_in[26];
    const float* bs2b      = (const float*)d_in[27];
    float* out = (float*)d_out;

    cudaFuncSetAttribute(mma_gemm_kernel<4>, cudaFuncAttributeMaxDynamicSharedMemorySize, SMEM_MT4);
    cudaFuncSetAttribute(mma_gemm_kernel<2>, cudaFuncAttributeMaxDynamicSharedMemorySize, SMEM_MT2);

    auto sym = [](const void* s) { void* p; cudaGetSymbolAddress(&p, s); return p; };
    GPtr eobj  = {(bf16*)sym(g_eobj_h),  (bf16*)sym(g_eobj_l)};
    GPtr epred = {(bf16*)sym(g_epred_h), (bf16*)sym(g_epred_l)};
    GPtr tobj  = {(bf16*)sym(g_tobj_h),  (bf16*)sym(g_tobj_l)};
    GPtr trel  = {(bf16*)sym(g_trel_h),  (bf16*)sym(g_trel_l)};
    GPtr objA  = {(bf16*)sym(g_objA_h),  (bf16*)sym(g_objA_l)};
    GPtr pA    = {(bf16*)sym(g_pA_h),    (bf16*)sym(g_pA_l)};
    GPtr hb    = {(bf16*)sym(g_h_h),     (bf16*)sym(g_h_l)};
    GPtr p512  = {(bf16*)sym(g_p512_h),  (bf16*)sym(g_p512_l)};
    GPtr pool  = {(bf16*)sym(g_pool_h),  (bf16*)sym(g_pool_l)};
    GPtr o512  = {(bf16*)sym(g_o512_h),  (bf16*)sym(g_o512_l)};
    bf16* wth = (bf16*)sym(g_wt_h);
    bf16* wtl = (bf16*)sym(g_wt_l);
    float* tbuf = (float*)sym(g_t);
    int* cnt = (int*)sym(g_cnt);
    int* off = (int*)sym(g_off);
    int* objarr = (int*)sym(g_objarr);
    int* entries = (int*)sym(g_entries);
    float* finv = (float*)sym(g_inv);

    // weight pool offsets (bf16 elems)
    size_t po = 0;
    auto take = [&](size_t n) { GPtr r = {wth + po, wtl + po}; po += n; return r; };
    GPtr tWfobj = take((size_t)DIN * KP_EMB);
    GPtr tWfrel = take((size_t)DIN * KP_EMB);
    GPtr tW1a   = take((size_t)H_DIM * 3 * DIN);
    GPtr tW1b   = take((size_t)1536 * H_DIM);
    GPtr tW2a   = take((size_t)H_DIM * H_DIM);
    GPtr tW2b   = take((size_t)DG * H_DIM);
    GPtr tWs1a  = take((size_t)L_EXTRA * H_DIM * 3 * DG);
    GPtr tWs1b  = take((size_t)L_EXTRA * 1536 * H_DIM);
    GPtr tWs2a  = take((size_t)L_EXTRA * H_DIM * H_DIM);
    GPtr tWs2b  = take((size_t)L_EXTRA * DG * H_DIM);

    auto ts = [](const float* B, GPtr Bt, int K, int N, int KP) {
        dim3 grid((KP + 31) / 32, (N + 31) / 32);
        tsplit_kernel<<<grid, dim3(32, 8)>>>(B, Bt.h, Bt.l, K, N, KP);
    };

    // --- prep: splits + transposes ---
    split_kernel<<<(O_N * DIN + 255) / 256, 256>>>(obj_embs, O_N * DIN, eobj.h, eobj.l);
    split_kernel<<<(T_N * DIN + 255) / 256, 256>>>(pred_embs, T_N * DIN, epred.h, epred.l);
    split_pad_kernel<<<1000, 256>>>(obj_table, 1000, DW, DWP, tobj.h, tobj.l);
    split_pad_kernel<<<500, 256>>>(rel_table, 500, DW, DWP, trel.h, trel.l);

    ts(Wf_obj, tWfobj, DIN + DW, DIN, KP_EMB);
    ts(Wf_rel, tWfrel, DIN + DW, DIN, KP_EMB);
    ts(W1a, tW1a, 3 * DIN, H_DIM, 3 * DIN);
    ts(W1b, tW1b, H_DIM, 1536, H_DIM);
    ts(W2a, tW2a, H_DIM, H_DIM, H_DIM);
    ts(W2b, tW2b, H_DIM, DG, H_DIM);
    for (int i = 0; i < L_EXTRA; i++) {
        ts(Ws1a + (size_t)i * 3 * DG * H_DIM, {tWs1a.h + (size_t)i * H_DIM * 3 * DG, tWs1a.l + (size_t)i * H_DIM * 3 * DG}, 3 * DG, H_DIM, 3 * DG);
        ts(Ws1b + (size_t)i * H_DIM * 1536,   {tWs1b.h + (size_t)i * 1536 * H_DIM,   tWs1b.l + (size_t)i * 1536 * H_DIM},   H_DIM, 1536, H_DIM);
        ts(Ws2a + (size_t)i * H_DIM * H_DIM,  {tWs2a.h + (size_t)i * H_DIM * H_DIM,  tWs2a.l + (size_t)i * H_DIM * H_DIM},  H_DIM, H_DIM, H_DIM);
        ts(Ws2b + (size_t)i * H_DIM * DG,     {tWs2b.h + (size_t)i * DG * H_DIM,     tWs2b.l + (size_t)i * DG * H_DIM},     H_DIM, DG, H_DIM);
    }

    // --- CSR for deterministic pooling ---
    zero_int_kernel<<<(O_N + 255) / 256, 256>>>(cnt, O_N);
    build_count_kernel<<<(E_N + 255) / 256, 256>>>(rels, objarr, cnt);
    scan_kernel<<<1, 1024>>>(cnt, off, finv);
    rank_fill_kernel<<<(O_N + 255) / 256, 256>>>(objarr, off, entries);

    GPtr nullg = {nullptr, nullptr};

    // --- embedding GEMMs (MT=2: better wave granularity) ---
    run_mma(2, O_N, DIN, KP_EMB, 1, DIN, eobj, DIN, tobj, DWP, nullptr, objs, 1,
            tWfobj, bf_obj, nullptr, objA, DIN);
    run_mma(2, T_N, DIN, KP_EMB, 1, DIN, epred, DIN, trel, DWP, nullptr, rels + 1, 3,
            tWfrel, bf_rel, nullptr, pA, DIN);

    // --- layer 0 ---
    run_mma(2, T_N, H_DIM, 3 * DIN, 2, DIN, objA, DIN, pA, DIN, rels, nullptr, 0,
            tW1a, b1a, nullptr, hb, H_DIM);
    run_mma(4, T_N, 1536, H_DIM, 0, 0, hb, H_DIM, nullg, 0, nullptr, nullptr, 0,
            tW1b, b1b, tbuf, nullg, 1536, nullptr, p512, 512, 1024);
    pool_gather_kernel<<<O_N, 256>>>(tbuf, entries, off, finv, pool.h, pool.l);
    run_mma(2, O_N, H_DIM, H_DIM, 0, 0, pool, 512, nullg, 0, nullptr, nullptr, 0,
            tW2a, b2a, nullptr, hb, H_DIM);
    run_mma(2, O_N, DG, H_DIM, 0, 0, hb, 512, nullg, 0, nullptr, nullptr, 0,
            tW2b, b2b, nullptr, o512, DG);

    // --- extra layers ---
    for (int i = 0; i < L_EXTRA; i++) {
        const bool last = (i == L_EXTRA - 1);
        GPtr w1a = {tWs1a.h + (size_t)i * H_DIM * 3 * DG, tWs1a.l + (size_t)i * H_DIM * 3 * DG};
        GPtr w1b = {tWs1b.h + (size_t)i * 1536 * H_DIM,   tWs1b.l + (size_t)i * 1536 * H_DIM};
        GPtr w2a = {tWs2a.h + (size_t)i * H_DIM * H_DIM,  tWs2a.l + (size_t)i * H_DIM * H_DIM};
        GPtr w2b = {tWs2b.h + (size_t)i * DG * H_DIM,     tWs2b.l + (size_t)i * DG * H_DIM};

        run_mma(2, T_N, H_DIM, 3 * DG, 2, DG, o512, DG, p512, DG, rels, nullptr, 0,
                w1a, bs1a + (size_t)i * H_DIM, nullptr, hb, H_DIM);
        run_mma(4, T_N, 1536, H_DIM, 0, 0, hb, H_DIM, nullg, 0, nullptr, nullptr, 0,
                w1b, bs1b + (size_t)i * 1536, tbuf, nullg, 1536,
                last ? (out + (size_t)O_N * DG) : nullptr,
                last ? nullg : p512, 512, 1024);
        pool_gather_kernel<<<O_N, 256>>>(tbuf, entries, off, finv, pool.h, pool.l);
        run_mma(2, O_N, H_DIM, H_DIM, 0, 0, pool, 512, nullg, 0, nullptr, nullptr, 0,
                w2a, bs2a + (size_t)i * H_DIM, nullptr, hb, H_DIM);
        run_mma(2, O_N, DG, H_DIM, 0, 0, hb, 512, nullg, 0, nullptr, nullptr, 0,
                w2b, bs2b + (size_t)i * DG,
                last ? out : nullptr, last ? nullg : o512, DG);
    }
}

// round 10
// speedup vs baseline: 3.4827x; 1.1273x over previous
#include <cuda_runtime.h>
#include <cuda_bf16.h>
#include <cstdint>

typedef __nv_bfloat16 bf16;

#define O_N 2000
#define T_N 6000
#define DIN 2048
#define DW 300
#define DWP 320
#define DG 512
#define H_DIM 512
#define L_EXTRA 4
#define E_N (2*T_N)
#define KP_EMB 2368

#define BN 128
#define BKC 64
#define ASTR 144

// ---------------- scratch (device globals) ----------------
__device__ __align__(16) bf16 g_eobj_h[O_N*DIN],  g_eobj_l[O_N*DIN];
__device__ __align__(16) bf16 g_epred_h[T_N*DIN], g_epred_l[T_N*DIN];
__device__ __align__(16) bf16 g_tobj_h[1000*DWP], g_tobj_l[1000*DWP];
__device__ __align__(16) bf16 g_trel_h[500*DWP],  g_trel_l[500*DWP];
__device__ __align__(16) bf16 g_objA_h[O_N*DIN],  g_objA_l[O_N*DIN];
__device__ __align__(16) bf16 g_pA_h[T_N*DIN],    g_pA_l[T_N*DIN];
__device__ __align__(16) bf16 g_h_h[T_N*512],     g_h_l[T_N*512];
__device__ __align__(16) bf16 g_p512_h[T_N*512],  g_p512_l[T_N*512];
__device__ __align__(16) bf16 g_pool_h[O_N*512],  g_pool_l[O_N*512];
__device__ __align__(16) bf16 g_o512_h[O_N*512],  g_o512_l[O_N*512];
__device__ __align__(16) float g_tblobj[1000*2048];
__device__ __align__(16) float g_tblrel[500*2048];
__device__ __align__(16) float g_objSO[O_N*1024];
#define WT_POOL 22544384
__device__ __align__(16) bf16 g_wt_h[WT_POOL], g_wt_l[WT_POOL];
__device__ __align__(16) float g_t[T_N * 1536];
__device__ int   g_cnt[O_N];
__device__ float g_inv[O_N];
__device__ int   g_off[O_N + 1];
__device__ int   g_objarr[E_N];
__device__ int   g_entries[E_N];

// ---------------- PTX helpers ----------------
__device__ __forceinline__ uint32_t smem_u32(const void* p) {
    uint32_t a;
    asm("{ .reg .u64 t; cvta.to.shared.u64 t, %1; cvt.u32.u64 %0, t; }" : "=r"(a) : "l"(p));
    return a;
}
__device__ __forceinline__ void cpa16(uint32_t dst, const void* src, uint32_t sz) {
    asm volatile("cp.async.cg.shared.global [%0], [%1], 16, %2;"
        :: "r"(dst), "l"(src), "r"(sz) : "memory");
}
__device__ __forceinline__ void cpa_commit() {
    asm volatile("cp.async.commit_group;" ::: "memory");
}
template<int N>
__device__ __forceinline__ void cpa_wait() {
    asm volatile("cp.async.wait_group %0;" :: "n"(N) : "memory");
}
__device__ __forceinline__ void ldsm4(uint32_t* r, uint32_t addr) {
    asm volatile("ldmatrix.sync.aligned.m8n8.x4.shared.b16 {%0,%1,%2,%3}, [%4];"
        : "=r"(r[0]), "=r"(r[1]), "=r"(r[2]), "=r"(r[3]) : "r"(addr));
}
__device__ __forceinline__ void mma16816(float* d, const uint32_t* a, const uint32_t* b) {
    asm volatile("mma.sync.aligned.m16n8k16.row.col.f32.bf16.bf16.f32 "
        "{%0,%1,%2,%3}, {%4,%5,%6,%7}, {%8,%9}, {%0,%1,%2,%3};"
        : "+f"(d[0]), "+f"(d[1]), "+f"(d[2]), "+f"(d[3])
        : "r"(a[0]), "r"(a[1]), "r"(a[2]), "r"(a[3]), "r"(b[0]), "r"(b[1]));
}
__device__ __forceinline__ void split1(float v, bf16& h, bf16& l) {
    h = __float2bfloat16_rn(v);
    l = __float2bfloat16_rn(v - __bfloat162float(h));
}

// ---------------- bf16x3 pipelined GEMM (mode-0 only, epilogue gather-adds) ----------------
// C = act(A @ Bt^T + bias + add0[idx0[row]] + add1[idx1[row]])
template<int MT>
__global__ __launch_bounds__(256, (MT == 2 ? 2 : 1))
void mma_gemm_kernel(int M, int K, int ldb, int do_relu,
                     const bf16* __restrict__ A0h, const bf16* __restrict__ A0l, int lda,
                     const bf16* __restrict__ Bh, const bf16* __restrict__ Bl,
                     const float* __restrict__ bias,
                     const float* __restrict__ add0, const int* __restrict__ idx0, int idx0s, int add0ld, int add0off,
                     const float* __restrict__ add1, const int* __restrict__ idx1, int idx1s, int add1ld, int add1off,
                     float* __restrict__ Cf, bf16* __restrict__ Ch, bf16* __restrict__ Cl, int ldc,
                     float* __restrict__ auxf, bf16* __restrict__ auxh, bf16* __restrict__ auxl,
                     int aux_lo, int aux_hi)
{
    constexpr int BM = 32 * MT;
    constexpr int ATILE = BM * ASTR;
    constexpr int BTILE = 128 * ASTR;
    constexpr int STAGE = 2 * ATILE + 2 * BTILE;

    extern __shared__ char smem[];
    const uint32_t sb = smem_u32(smem);
    const int tid = threadIdx.x;
    const int lane = tid & 31;
    const int wid = tid >> 5;
    const int bm = blockIdx.y * BM;
    const int bn = blockIdx.x * BN;

    const int c = tid & 7;
    const int rl = tid >> 3;
    const bf16* pAh[MT]; const bf16* pAl[MT];
    uint32_t asz[MT];
    #pragma unroll
    for (int i = 0; i < MT; i++) {
        int arow = bm + rl + 32 * i;
        bool v = arow < M;
        asz[i] = v ? 16u : 0u;
        int ar = v ? arow : 0;
        pAh[i] = A0h + (size_t)ar * lda;
        pAl[i] = A0l + (size_t)ar * lda;
    }
    const bf16* pBh[4]; const bf16* pBl[4];
    #pragma unroll
    for (int i = 0; i < 4; i++) {
        int r = bn + rl + 32 * i;
        pBh[i] = Bh + (size_t)r * ldb;
        pBl[i] = Bl + (size_t)r * ldb;
    }

    float acc[MT][4][4];
    #pragma unroll
    for (int a = 0; a < MT; a++)
        #pragma unroll
        for (int b = 0; b < 4; b++)
            #pragma unroll
            for (int d = 0; d < 4; d++) acc[a][b][d] = 0.f;

    const int wr = wid & 1;
    const int wc = wid >> 1;
    const uint32_t a_l_off = (uint32_t)((lane & 15) * ASTR + (lane >> 4) * 16);
    const uint32_t b_l_off = (uint32_t)((((lane & 7) + ((lane >> 4) << 3)) * ASTR) + (((lane >> 3) & 1) << 4));

    const int NT = K / BKC;

    auto issue = [&](int it) {
        const uint32_t st = sb + (uint32_t)(it & 1) * STAGE;
        const int k0 = it * BKC + c * 8;
        #pragma unroll
        for (int i = 0; i < MT; i++) {
            uint32_t d = st + (uint32_t)((rl + 32 * i) * ASTR + c * 16);
            cpa16(d,         pAh[i] + k0, asz[i]);
            cpa16(d + ATILE, pAl[i] + k0, asz[i]);
        }
        #pragma unroll
        for (int i = 0; i < 4; i++) {
            uint32_t d = st + 2 * ATILE + (uint32_t)((rl + 32 * i) * ASTR + c * 16);
            cpa16(d,         pBh[i] + k0, 16u);
            cpa16(d + BTILE, pBl[i] + k0, 16u);
        }
        cpa_commit();
    };

    issue(0);

    for (int it = 0; it < NT; it++) {
        if (it + 1 < NT) { issue(it + 1); cpa_wait<1>(); }
        else             { cpa_wait<0>(); }
        __syncthreads();

        const uint32_t st = sb + (uint32_t)(it & 1) * STAGE;
        const uint32_t aH = st + (uint32_t)(wr * 16 * MT * ASTR) + a_l_off;
        const uint32_t aL = aH + ATILE;
        const uint32_t bH = st + 2 * ATILE + (uint32_t)(wc * 32 * ASTR) + b_l_off;
        const uint32_t bL = bH + BTILE;

        #pragma unroll
        for (int ks = 0; ks < 4; ks++) {
            const uint32_t kb = ks * 32;
            uint32_t af[MT][4], bh2[2][4];
            #pragma unroll
            for (int mt = 0; mt < MT; mt++) ldsm4(af[mt], aH + (uint32_t)(mt * 16 * ASTR) + kb);
            #pragma unroll
            for (int np = 0; np < 2; np++) ldsm4(bh2[np], bH + (uint32_t)(np * 16 * ASTR) + kb);
            #pragma unroll
            for (int mt = 0; mt < MT; mt++)
                #pragma unroll
                for (int np = 0; np < 2; np++) {
                    mma16816(acc[mt][2 * np],     af[mt], &bh2[np][0]);
                    mma16816(acc[mt][2 * np + 1], af[mt], &bh2[np][2]);
                }
            uint32_t bl2[2][4];
            #pragma unroll
            for (int np = 0; np < 2; np++) ldsm4(bl2[np], bL + (uint32_t)(np * 16 * ASTR) + kb);
            #pragma unroll
            for (int mt = 0; mt < MT; mt++)
                #pragma unroll
                for (int np = 0; np < 2; np++) {
                    mma16816(acc[mt][2 * np],     af[mt], &bl2[np][0]);
                    mma16816(acc[mt][2 * np + 1], af[mt], &bl2[np][2]);
                }
            #pragma unroll
            for (int mt = 0; mt < MT; mt++) ldsm4(af[mt], aL + (uint32_t)(mt * 16 * ASTR) + kb);
            #pragma unroll
            for (int mt = 0; mt < MT; mt++)
                #pragma unroll
                for (int np = 0; np < 2; np++) {
                    mma16816(acc[mt][2 * np],     af[mt], &bh2[np][0]);
                    mma16816(acc[mt][2 * np + 1], af[mt], &bh2[np][2]);
                }
        }
        __syncthreads();
    }

    // ---- epilogue ----
    const int g = lane >> 2, qr = lane & 3;
    const int awidth = aux_hi - aux_lo;
    // per-(mt,hh) row + gathered row bases
    const float* a0p[MT][2];
    const float* a1p[MT][2];
    #pragma unroll
    for (int mt = 0; mt < MT; mt++)
        #pragma unroll
        for (int hh = 0; hh < 2; hh++) {
            int row = bm + wr * 16 * MT + mt * 16 + g + 8 * hh;
            int rr = (row < M) ? row : 0;
            a0p[mt][hh] = add0 ? add0 + (size_t)idx0[(size_t)rr * idx0s] * add0ld + add0off : nullptr;
            a1p[mt][hh] = add1 ? add1 + (size_t)idx1[(size_t)rr * idx1s] * add1ld + add1off : nullptr;
        }
    #pragma unroll
    for (int nt = 0; nt < 4; nt++) {
        const int col = bn + wc * 32 + nt * 8 + qr * 2;
        float2 bv = make_float2(0.f, 0.f);
        if (bias) bv = *reinterpret_cast<const float2*>(bias + col);
        const bool in_aux = (col >= aux_lo) && (col < aux_hi);
        #pragma unroll
        for (int mt = 0; mt < MT; mt++) {
            #pragma unroll
            for (int hh = 0; hh < 2; hh++) {
                const int row = bm + wr * 16 * MT + mt * 16 + g + 8 * hh;
                if (row >= M) continue;
                float v0 = acc[mt][nt][2 * hh]     + bv.x;
                float v1 = acc[mt][nt][2 * hh + 1] + bv.y;
                if (add0) {
                    float2 a = *reinterpret_cast<const float2*>(a0p[mt][hh] + col);
                    v0 += a.x; v1 += a.y;
                }
                if (add1) {
                    float2 a = *reinterpret_cast<const float2*>(a1p[mt][hh] + col);
                    v0 += a.x; v1 += a.y;
                }
                if (do_relu) { v0 = fmaxf(v0, 0.f); v1 = fmaxf(v1, 0.f); }
                if (Cf)
                    *reinterpret_cast<float2*>(Cf + (size_t)row * ldc + col) = make_float2(v0, v1);
                if (Ch) {
                    bf16 h0, l0, h1, l1;
                    split1(v0, h0, l0); split1(v1, h1, l1);
                    __nv_bfloat162 ph; ph.x = h0; ph.y = h1;
                    __nv_bfloat162 pl; pl.x = l0; pl.y = l1;
                    *reinterpret_cast<__nv_bfloat162*>(Ch + (size_t)row * ldc + col) = ph;
                    *reinterpret_cast<__nv_bfloat162*>(Cl + (size_t)row * ldc + col) = pl;
                }
                if (in_aux) {
                    const int ac = col - aux_lo;
                    if (auxf)
                        *reinterpret_cast<float2*>(auxf + (size_t)row * awidth + ac) = make_float2(v0, v1);
                    if (auxh) {
                        bf16 h0, l0, h1, l1;
                        split1(v0, h0, l0); split1(v1, h1, l1);
                        __nv_bfloat162 ph; ph.x = h0; ph.y = h1;
                        __nv_bfloat162 pl; pl.x = l0; pl.y = l1;
                        *reinterpret_cast<__nv_bfloat162*>(auxh + (size_t)row * awidth + ac) = ph;
                        *reinterpret_cast<__nv_bfloat162*>(auxl + (size_t)row * awidth + ac) = pl;
                    }
                }
            }
        }
    }
}

// ---------------- prep kernels ----------------
__global__ void split_kernel(const float* __restrict__ x, int n,
                             bf16* __restrict__ h, bf16* __restrict__ l) {
    int i = blockIdx.x * blockDim.x + threadIdx.x;
    if (i >= n) return;
    float v = x[i];
    bf16 hh, ll; split1(v, hh, ll);
    h[i] = hh; l[i] = ll;
}
__global__ void split_pad_kernel(const float* __restrict__ x, int V, int W, int WP,
                                 bf16* __restrict__ h, bf16* __restrict__ l) {
    int v = blockIdx.x;
    for (int c = threadIdx.x; c < WP; c += blockDim.x) {
        float val = (c < W) ? x[(size_t)v * W + c] : 0.f;
        bf16 hh, ll; split1(val, hh, ll);
        h[(size_t)v * WP + c] = hh;
        l[(size_t)v * WP + c] = ll;
    }
}
__global__ void tsplit_kernel(const float* __restrict__ B, bf16* __restrict__ Bth,
                              bf16* __restrict__ Btl, int K, int N, int KP) {
    __shared__ float tile[32][33];
    int bk = blockIdx.x * 32, bn = blockIdx.y * 32;
    int x = threadIdx.x, y = threadIdx.y;
    for (int i = y; i < 32; i += 8) {
        int k = bk + i, n = bn + x;
        tile[i][x] = (k < K && n < N) ? B[(size_t)k * N + n] : 0.f;
    }
    __syncthreads();
    for (int i = y; i < 32; i += 8) {
        int n = bn + i, k = bk + x;
        if (n < N && k < KP) {
            float v = tile[x][i];
            bf16 hh, ll; split1(v, hh, ll);
            Bth[(size_t)n * KP + k] = hh;
            Btl[(size_t)n * KP + k] = ll;
        }
    }
}

// ---------------- deterministic scatter-mean pooling ----------------
__global__ void zero_int_kernel(int* p, int n) {
    int i = blockIdx.x * blockDim.x + threadIdx.x;
    if (i < n) p[i] = 0;
}
__global__ void build_count_kernel(const int* __restrict__ rels, int* __restrict__ objarr,
                                   int* __restrict__ cnt) {
    int e = blockIdx.x * blockDim.x + threadIdx.x;
    if (e >= E_N) return;
    int t = e >> 1;
    int v = rels[3 * t + ((e & 1) ? 2 : 0)];
    objarr[e] = v;
    atomicAdd(&cnt[v], 1);
}
__global__ void scan_kernel(const int* __restrict__ cnt, int* __restrict__ off,
                            float* __restrict__ inv) {
    __shared__ int buf[2][2048];
    int tid = threadIdx.x;
    for (int i = tid; i < 2048; i += 1024) {
        int c = (i < O_N) ? cnt[i] : 0;
        buf[0][i] = c;
        if (i < O_N) inv[i] = 1.0f / fmaxf((float)c, 1.0f);
    }
    __syncthreads();
    int src = 0;
    for (int d = 1; d < 2048; d <<= 1) {
        for (int i = tid; i < 2048; i += 1024) {
            int v = buf[src][i];
            if (i >= d) v += buf[src][i - d];
            buf[1 - src][i] = v;
        }
        src = 1 - src;
        __syncthreads();
    }
    for (int i = tid; i < O_N; i += 1024) off[i] = (i == 0) ? 0 : buf[src][i - 1];
    if (tid == 0) off[O_N] = buf[src][O_N - 1];
}
__global__ void rank_fill_kernel(const int* __restrict__ objarr, const int* __restrict__ off,
                                 int* __restrict__ entries) {
    int i = blockIdx.x * blockDim.x + threadIdx.x;
    if (i >= O_N) return;
    int w = off[i];
    for (int e = 0; e < E_N; e++)
        if (objarr[e] == i) entries[w++] = e;
}
__global__ void pool_gather_kernel(const float* __restrict__ t,
                                   const int* __restrict__ entries, const int* __restrict__ off,
                                   const float* __restrict__ inv,
                                   bf16* __restrict__ ph, bf16* __restrict__ pl) {
    int i = blockIdx.x;
    int c0 = threadIdx.x;
    int beg = off[i], end = off[i + 1];
    float s0 = 0.f, s1 = 0.f;
    for (int p = beg; p < end; p++) {
        int e = entries[p];
        int tr = e >> 1;
        const float* src = t + (size_t)tr * 1536 + ((e & 1) ? 1024 : 0);
        s0 += src[c0];
        s1 += src[c0 + 256];
    }
    float iv = inv[i];
    float v0 = s0 * iv, v1 = s1 * iv;
    bf16 h, l;
    split1(v0, h, l);
    ph[(size_t)i * 512 + c0] = h; pl[(size_t)i * 512 + c0] = l;
    split1(v1, h, l);
    ph[(size_t)i * 512 + c0 + 256] = h; pl[(size_t)i * 512 + c0 + 256] = l;
}

// ---------------- host glue ----------------
struct GPtr { bf16 *h, *l; };

#define SMEM_MT4 (2 * (2*128*ASTR + 2*128*ASTR))
#define SMEM_MT2 (2 * (2*64*ASTR + 2*128*ASTR))

struct AddArg { const float* p; const int* idx; int s; int ld; int off; };

static inline void run_mma(int MT, int M, int Ntot, int K, int ldb, int relu,
                           GPtr A0, int lda, GPtr Bt,
                           const float* bias,
                           float* Cf, GPtr C, int ldc,
                           AddArg a0 = {nullptr, nullptr, 0, 0, 0},
                           AddArg a1 = {nullptr, nullptr, 0, 0, 0},
                           float* auxf = nullptr, GPtr aux = {nullptr, nullptr},
                           int aux_lo = 0, int aux_hi = 0)
{
    if (MT == 4) {
        dim3 grid(Ntot / BN, (M + 127) / 128);
        mma_gemm_kernel<4><<<grid, 256, SMEM_MT4>>>(M, K, ldb, relu,
            A0.h, A0.l, lda, Bt.h, Bt.l, bias,
            a0.p, a0.idx, a0.s, a0.ld, a0.off,
            a1.p, a1.idx, a1.s, a1.ld, a1.off,
            Cf, C.h, C.l, ldc, auxf, aux.h, aux.l, aux_lo, aux_hi);
    } else {
        dim3 grid(Ntot / BN, (M + 63) / 64);
        mma_gemm_kernel<2><<<grid, 256, SMEM_MT2>>>(M, K, ldb, relu,
            A0.h, A0.l, lda, Bt.h, Bt.l, bias,
            a0.p, a0.idx, a0.s, a0.ld, a0.off,
            a1.p, a1.idx, a1.s, a1.ld, a1.off,
            Cf, C.h, C.l, ldc, auxf, aux.h, aux.l, aux_lo, aux_hi);
    }
}

extern "C" void kernel_launch(void* const* d_in, const int* in_sizes, int n_in,
                              void* d_out, int out_size)
{
    const float* obj_embs  = (const float*)d_in[0];
    const float* pred_embs = (const float*)d_in[2];
    const int*   rels      = (const int*)d_in[4];
    const int*   objs      = (const int*)d_in[5];
    const float* obj_table = (const float*)d_in[6];
    const float* rel_table = (const float*)d_in[7];
    const float* Wf_obj    = (const float*)d_in[8];
    const float* bf_obj    = (const float*)d_in[9];
    const float* Wf_rel    = (const float*)d_in[10];
    const float* bf_rel    = (const float*)d_in[11];
    const float* W1a       = (const float*)d_in[12];
    const float* b1a       = (const float*)d_in[13];
    const float* W1b       = (const float*)d_in[14];
    const float* b1b       = (const float*)d_in[15];
    const float* W2a       = (const float*)d_in[16];
    const float* b2a       = (const float*)d_in[17];
    const float* W2b       = (const float*)d_in[18];
    const float* b2b       = (const float*)d_in[19];
    const float* Ws1a      = (const float*)d_in[20];
    const float* bs1a      = (const float*)d_in[21];
    const float* Ws1b      = (const float*)d_in[22];
    const float* bs1b      = (const float*)d_in[23];
    const float* Ws2a      = (const float*)d_in[24];
    const float* bs2a      = (const float*)d_in[25];
    const float* Ws2b      = (const float*)d_in[26];
    const float* bs2b      = (const float*)d_in[27];
    float* out = (float*)d_out;

    cudaFuncSetAttribute(mma_gemm_kernel<4>, cudaFuncAttributeMaxDynamicSharedMemorySize, SMEM_MT4);
    cudaFuncSetAttribute(mma_gemm_kernel<2>, cudaFuncAttributeMaxDynamicSharedMemorySize, SMEM_MT2);

    auto sym = [](const void* s) { void* p; cudaGetSymbolAddress(&p, s); return p; };
    GPtr eobj  = {(bf16*)sym(g_eobj_h),  (bf16*)sym(g_eobj_l)};
    GPtr epred = {(bf16*)sym(g_epred_h), (bf16*)sym(g_epred_l)};
    GPtr tobj  = {(bf16*)sym(g_tobj_h),  (bf16*)sym(g_tobj_l)};
    GPtr trel  = {(bf16*)sym(g_trel_h),  (bf16*)sym(g_trel_l)};
    GPtr objA  = {(bf16*)sym(g_objA_h),  (bf16*)sym(g_objA_l)};
    GPtr pA    = {(bf16*)sym(g_pA_h),    (bf16*)sym(g_pA_l)};
    GPtr hb    = {(bf16*)sym(g_h_h),     (bf16*)sym(g_h_l)};
    GPtr p512  = {(bf16*)sym(g_p512_h),  (bf16*)sym(g_p512_l)};
    GPtr pool  = {(bf16*)sym(g_pool_h),  (bf16*)sym(g_pool_l)};
    GPtr o512  = {(bf16*)sym(g_o512_h),  (bf16*)sym(g_o512_l)};
    float* tblobj = (float*)sym(g_tblobj);
    float* tblrel = (float*)sym(g_tblrel);
    float* objSO  = (float*)sym(g_objSO);
    bf16* wth = (bf16*)sym(g_wt_h);
    bf16* wtl = (bf16*)sym(g_wt_l);
    float* tbuf = (float*)sym(g_t);
    int* cnt = (int*)sym(g_cnt);
    int* off = (int*)sym(g_off);
    int* objarr = (int*)sym(g_objarr);
    int* entries = (int*)sym(g_entries);
    float* finv = (float*)sym(g_inv);

    // weight pool (bf16 elems)
    size_t po = 0;
    auto take = [&](size_t n) { GPtr r = {wth + po, wtl + po}; po += n; return r; };
    GPtr tWfobj  = take((size_t)DIN * KP_EMB);        // [2048, 2368]
    GPtr tWfrel  = take((size_t)DIN * KP_EMB);
    GPtr tW1a_p  = take((size_t)H_DIM * DIN);          // [512, 2048]
    GPtr tW1a_so = take((size_t)1024 * DIN);           // [1024, 2048]
    GPtr tW1b    = take((size_t)1536 * H_DIM);
    GPtr tW2a    = take((size_t)H_DIM * H_DIM);
    GPtr tW2b    = take((size_t)DG * H_DIM);
    GPtr tWs1a_p  = take((size_t)L_EXTRA * H_DIM * DG);    // [512,512] x4
    GPtr tWs1a_so = take((size_t)L_EXTRA * 1024 * DG);     // [1024,512] x4
    GPtr tWs1b    = take((size_t)L_EXTRA * 1536 * H_DIM);
    GPtr tWs2a    = take((size_t)L_EXTRA * H_DIM * H_DIM);
    GPtr tWs2b    = take((size_t)L_EXTRA * DG * H_DIM);

    auto ts = [](const float* B, GPtr Bt, int K, int N, int KP) {
        dim3 grid((KP + 31) / 32, (N + 31) / 32);
        tsplit_kernel<<<grid, dim3(32, 8)>>>(B, Bt.h, Bt.l, K, N, KP);
    };

    // --- prep ---
    split_kernel<<<(O_N * DIN + 255) / 256, 256>>>(obj_embs, O_N * DIN, eobj.h, eobj.l);
    split_kernel<<<(T_N * DIN + 255) / 256, 256>>>(pred_embs, T_N * DIN, epred.h, epred.l);
    split_pad_kernel<<<1000, 256>>>(obj_table, 1000, DW, DWP, tobj.h, tobj.l);
    split_pad_kernel<<<500, 256>>>(rel_table, 500, DW, DWP, trel.h, trel.l);

    ts(Wf_obj, tWfobj, DIN + DW, DIN, KP_EMB);
    ts(Wf_rel, tWfrel, DIN + DW, DIN, KP_EMB);
    // W1a [6144,512]: s rows 0..2047, p rows 2048..4095, o rows 4096..6143
    ts(W1a + (size_t)DIN * H_DIM, tW1a_p, DIN, H_DIM, DIN);
    ts(W1a, tW1a_so, DIN, H_DIM, DIN);
    ts(W1a + (size_t)2 * DIN * H_DIM, {tW1a_so.h + (size_t)H_DIM * DIN, tW1a_so.l + (size_t)H_DIM * DIN}, DIN, H_DIM, DIN);
    ts(W1b, tW1b, H_DIM, 1536, H_DIM);
    ts(W2a, tW2a, H_DIM, H_DIM, H_DIM);
    ts(W2b, tW2b, H_DIM, DG, H_DIM);
    for (int i = 0; i < L_EXTRA; i++) {
        const float* Wi = Ws1a + (size_t)i * 3 * DG * H_DIM;   // [1536, 512]
        GPtr p_i  = {tWs1a_p.h + (size_t)i * H_DIM * DG,  tWs1a_p.l + (size_t)i * H_DIM * DG};
        GPtr so_i = {tWs1a_so.h + (size_t)i * 1024 * DG,  tWs1a_so.l + (size_t)i * 1024 * DG};
        ts(Wi + (size_t)DG * H_DIM, p_i, DG, H_DIM, DG);
        ts(Wi, so_i, DG, H_DIM, DG);
        ts(Wi + (size_t)2 * DG * H_DIM, {so_i.h + (size_t)H_DIM * DG, so_i.l + (size_t)H_DIM * DG}, DG, H_DIM, DG);
        ts(Ws1b + (size_t)i * H_DIM * 1536, {tWs1b.h + (size_t)i * 1536 * H_DIM, tWs1b.l + (size_t)i * 1536 * H_DIM}, H_DIM, 1536, H_DIM);
        ts(Ws2a + (size_t)i * H_DIM * H_DIM, {tWs2a.h + (size_t)i * H_DIM * H_DIM, tWs2a.l + (size_t)i * H_DIM * H_DIM}, H_DIM, H_DIM, H_DIM);
        ts(Ws2b + (size_t)i * H_DIM * DG, {tWs2b.h + (size_t)i * DG * H_DIM, tWs2b.l + (size_t)i * DG * H_DIM}, H_DIM, DG, H_DIM);
    }

    // --- CSR for deterministic pooling ---
    zero_int_kernel<<<(O_N + 255) / 256, 256>>>(cnt, O_N);
    build_count_kernel<<<(E_N + 255) / 256, 256>>>(rels, objarr, cnt);
    scan_kernel<<<1, 1024>>>(cnt, off, finv);
    rank_fill_kernel<<<(O_N + 255) / 256, 256>>>(objarr, off, entries);

    GPtr nullg = {nullptr, nullptr};
    AddArg noadd = {nullptr, nullptr, 0, 0, 0};

    // --- table contributions (small GEMMs, no bias/relu) ---
    run_mma(2, 1000, DIN, DWP, KP_EMB, 0, tobj, DWP,
            {tWfobj.h + DIN, tWfobj.l + DIN}, nullptr, tblobj, nullg, DIN);
    run_mma(2, 500, DIN, DWP, KP_EMB, 0, trel, DWP,
            {tWfrel.h + DIN, tWfrel.l + DIN}, nullptr, tblrel, nullg, DIN);

    // --- embedding GEMMs (K=2048 main part + epilogue table add) ---
    run_mma(4, O_N, DIN, DIN, KP_EMB, 1, eobj, DIN, tWfobj, bf_obj,
            nullptr, objA, DIN, {tblobj, objs, 1, DIN, 0});
    run_mma(4, T_N, DIN, DIN, KP_EMB, 1, epred, DIN, tWfrel, bf_rel,
            nullptr, pA, DIN, {tblrel, rels + 1, 3, DIN, 0});

    // --- layer 0 ---
    run_mma(2, O_N, 1024, DIN, DIN, 0, objA, DIN, tW1a_so, nullptr,
            objSO, nullg, 1024);
    run_mma(2, T_N, H_DIM, DIN, DIN, 1, pA, DIN, tW1a_p, b1a,
            nullptr, hb, H_DIM,
            {objSO, rels, 3, 1024, 0}, {objSO, rels + 2, 3, 1024, 512});
    run_mma(4, T_N, 1536, H_DIM, H_DIM, 1, hb, H_DIM, tW1b, b1b,
            tbuf, nullg, 1536, noadd, noadd, nullptr, p512, 512, 1024);
    pool_gather_kernel<<<O_N, 256>>>(tbuf, entries, off, finv, pool.h, pool.l);
    run_mma(2, O_N, H_DIM, H_DIM, H_DIM, 1, pool, 512, tW2a, b2a,
            nullptr, hb, H_DIM);
    run_mma(2, O_N, DG, H_DIM, H_DIM, 1, hb, 512, tW2b, b2b,
            nullptr, o512, DG);

    // --- extra layers ---
    for (int i = 0; i < L_EXTRA; i++) {
        const bool last = (i == L_EXTRA - 1);
        GPtr p_i  = {tWs1a_p.h + (size_t)i * H_DIM * DG,  tWs1a_p.l + (size_t)i * H_DIM * DG};
        GPtr so_i = {tWs1a_so.h + (size_t)i * 1024 * DG,  tWs1a_so.l + (size_t)i * 1024 * DG};
        GPtr w1b = {tWs1b.h + (size_t)i * 1536 * H_DIM,   tWs1b.l + (size_t)i * 1536 * H_DIM};
        GPtr w2a = {tWs2a.h + (size_t)i * H_DIM * H_DIM,  tWs2a.l + (size_t)i * H_DIM * H_DIM};
        GPtr w2b = {tWs2b.h + (size_t)i * DG * H_DIM,     tWs2b.l + (size_t)i * DG * H_DIM};

        run_mma(2, O_N, 1024, DG, DG, 0, o512, DG, so_i, nullptr,
                objSO, nullg, 1024);
        run_mma(2, T_N, H_DIM, DG, DG, 1, p512, DG, p_i, bs1a + (size_t)i * H_DIM,
                nullptr, hb, H_DIM,
                {objSO, rels, 3, 1024, 0}, {objSO, rels + 2, 3, 1024, 512});
        run_mma(4, T_N, 1536, H_DIM, H_DIM, 1, hb, H_DIM, w1b, bs1b + (size_t)i * 1536,
                tbuf, nullg, 1536, noadd, noadd,
                last ? (out + (size_t)O_N * DG) : nullptr,
                last ? nullg : p512, 512, 1024);
        pool_gather_kernel<<<O_N, 256>>>(tbuf, entries, off, finv, pool.h, pool.l);
        run_mma(2, O_N, H_DIM, H_DIM, H_DIM, 1, pool, 512, w2a, bs2a + (size_t)i * H_DIM,
                nullptr, hb, H_DIM);
        run_mma(2, O_N, DG, H_DIM, H_DIM, 1, hb, 512, w2b, bs2b + (size_t)i * DG,
                last ? out : nullptr, last ? nullg : o512, DG);
    }
}

// round 11
// speedup vs baseline: 3.6133x; 1.0375x over previous
#include <cuda_runtime.h>
#include <cuda_bf16.h>
#include <cstdint>

typedef __nv_bfloat16 bf16;

#define O_N 2000
#define T_N 6000
#define DIN 2048
#define DW 300
#define DWP 320
#define DG 512
#define H_DIM 512
#define L_EXTRA 4
#define E_N (2*T_N)
#define KP_EMB 2368

#define BN 128
#define BKC 64
#define ASTR 144

// ---------------- scratch (device globals) ----------------
__device__ __align__(16) bf16 g_eobj_h[O_N*DIN],  g_eobj_l[O_N*DIN];
__device__ __align__(16) bf16 g_epred_h[T_N*DIN], g_epred_l[T_N*DIN];
__device__ __align__(16) bf16 g_tobj_h[1000*DWP], g_tobj_l[1000*DWP];
__device__ __align__(16) bf16 g_trel_h[500*DWP],  g_trel_l[500*DWP];
__device__ __align__(16) bf16 g_objA_h[O_N*DIN],  g_objA_l[O_N*DIN];
__device__ __align__(16) bf16 g_pA_h[T_N*DIN],    g_pA_l[T_N*DIN];
__device__ __align__(16) bf16 g_h_h[T_N*512],     g_h_l[T_N*512];
__device__ __align__(16) bf16 g_p512_h[T_N*512],  g_p512_l[T_N*512];
__device__ __align__(16) bf16 g_pool_h[O_N*512],  g_pool_l[O_N*512];
__device__ __align__(16) bf16 g_o512_h[O_N*512],  g_o512_l[O_N*512];
__device__ __align__(16) float g_tblobj[1000*2048];
__device__ __align__(16) float g_tblrel[500*2048];
__device__ __align__(16) float g_objSO[O_N*1024];
#define WT_POOL 22544384
__device__ __align__(16) bf16 g_wt_h[WT_POOL], g_wt_l[WT_POOL];
__device__ __align__(16) float g_t[T_N * 1536];
__device__ int   g_cnt[O_N];
__device__ float g_inv[O_N];
__device__ int   g_off[O_N + 1];
__device__ int   g_objarr[E_N];
__device__ int   g_entries[E_N];

// ---------------- PTX helpers ----------------
__device__ __forceinline__ uint32_t smem_u32(const void* p) {
    uint32_t a;
    asm("{ .reg .u64 t; cvta.to.shared.u64 t, %1; cvt.u32.u64 %0, t; }" : "=r"(a) : "l"(p));
    return a;
}
__device__ __forceinline__ void cpa16(uint32_t dst, const void* src, uint32_t sz) {
    asm volatile("cp.async.cg.shared.global [%0], [%1], 16, %2;"
        :: "r"(dst), "l"(src), "r"(sz) : "memory");
}
__device__ __forceinline__ void cpa_commit() {
    asm volatile("cp.async.commit_group;" ::: "memory");
}
template<int N>
__device__ __forceinline__ void cpa_wait() {
    asm volatile("cp.async.wait_group %0;" :: "n"(N) : "memory");
}
__device__ __forceinline__ void ldsm4(uint32_t* r, uint32_t addr) {
    asm volatile("ldmatrix.sync.aligned.m8n8.x4.shared.b16 {%0,%1,%2,%3}, [%4];"
        : "=r"(r[0]), "=r"(r[1]), "=r"(r[2]), "=r"(r[3]) : "r"(addr));
}
__device__ __forceinline__ void mma16816(float* d, const uint32_t* a, const uint32_t* b) {
    asm volatile("mma.sync.aligned.m16n8k16.row.col.f32.bf16.bf16.f32 "
        "{%0,%1,%2,%3}, {%4,%5,%6,%7}, {%8,%9}, {%0,%1,%2,%3};"
        : "+f"(d[0]), "+f"(d[1]), "+f"(d[2]), "+f"(d[3])
        : "r"(a[0]), "r"(a[1]), "r"(a[2]), "r"(a[3]), "r"(b[0]), "r"(b[1]));
}
__device__ __forceinline__ void split1(float v, bf16& h, bf16& l) {
    h = __float2bfloat16_rn(v);
    l = __float2bfloat16_rn(v - __bfloat162float(h));
}

// ---------------- bf16x3 pipelined GEMM ----------------
// C = act(A @ Bt^T + bias + add0[idx0[row]] + add1[idx1[row]])
template<int MT>
__global__ __launch_bounds__(256, (MT == 4 ? 1 : 2))
void mma_gemm_kernel(int M, int K, int ldb, int do_relu, int skip_mid,
                     const bf16* __restrict__ A0h, const bf16* __restrict__ A0l, int lda,
                     const bf16* __restrict__ Bh, const bf16* __restrict__ Bl,
                     const float* __restrict__ bias,
                     const float* __restrict__ add0, const int* __restrict__ idx0, int idx0s, int add0ld, int add0off,
                     const float* __restrict__ add1, const int* __restrict__ idx1, int idx1s, int add1ld, int add1off,
                     float* __restrict__ Cf, bf16* __restrict__ Ch, bf16* __restrict__ Cl, int ldc,
                     float* __restrict__ auxf, bf16* __restrict__ auxh, bf16* __restrict__ auxl,
                     int aux_lo, int aux_hi)
{
    constexpr int BM = 32 * MT;
    constexpr int ATILE = BM * ASTR;
    constexpr int BTILE = 128 * ASTR;
    constexpr int STAGE = 2 * ATILE + 2 * BTILE;

    extern __shared__ char smem[];
    const uint32_t sb = smem_u32(smem);
    const int tid = threadIdx.x;
    const int lane = tid & 31;
    const int wid = tid >> 5;
    const int bm = blockIdx.y * BM;
    const int bn = blockIdx.x * BN;

    const int c = tid & 7;
    const int rl = tid >> 3;
    const bf16* pAh[MT]; const bf16* pAl[MT];
    uint32_t asz[MT];
    #pragma unroll
    for (int i = 0; i < MT; i++) {
        int arow = bm + rl + 32 * i;
        bool v = arow < M;
        asz[i] = v ? 16u : 0u;
        int ar = v ? arow : 0;
        pAh[i] = A0h + (size_t)ar * lda;
        pAl[i] = A0l + (size_t)ar * lda;
    }
    const bf16* pBh[4]; const bf16* pBl[4];
    #pragma unroll
    for (int i = 0; i < 4; i++) {
        int r = bn + rl + 32 * i;
        pBh[i] = Bh + (size_t)r * ldb;
        pBl[i] = Bl + (size_t)r * ldb;
    }

    float acc[MT][4][4];
    #pragma unroll
    for (int a = 0; a < MT; a++)
        #pragma unroll
        for (int b = 0; b < 4; b++)
            #pragma unroll
            for (int d = 0; d < 4; d++) acc[a][b][d] = 0.f;

    const int wr = wid & 1;
    const int wc = wid >> 1;
    const uint32_t a_l_off = (uint32_t)((lane & 15) * ASTR + (lane >> 4) * 16);
    const uint32_t b_l_off = (uint32_t)((((lane & 7) + ((lane >> 4) << 3)) * ASTR) + (((lane >> 3) & 1) << 4));

    const int NT = K / BKC;

    auto issue = [&](int it) {
        const uint32_t st = sb + (uint32_t)(it & 1) * STAGE;
        const int k0 = it * BKC + c * 8;
        #pragma unroll
        for (int i = 0; i < MT; i++) {
            uint32_t d = st + (uint32_t)((rl + 32 * i) * ASTR + c * 16);
            cpa16(d,         pAh[i] + k0, asz[i]);
            cpa16(d + ATILE, pAl[i] + k0, asz[i]);
        }
        #pragma unroll
        for (int i = 0; i < 4; i++) {
            uint32_t d = st + 2 * ATILE + (uint32_t)((rl + 32 * i) * ASTR + c * 16);
            cpa16(d,         pBh[i] + k0, 16u);
            cpa16(d + BTILE, pBl[i] + k0, 16u);
        }
        cpa_commit();
    };

    issue(0);

    for (int it = 0; it < NT; it++) {
        if (it + 1 < NT) { issue(it + 1); cpa_wait<1>(); }
        else             { cpa_wait<0>(); }
        __syncthreads();

        const uint32_t st = sb + (uint32_t)(it & 1) * STAGE;
        const uint32_t aH = st + (uint32_t)(wr * 16 * MT * ASTR) + a_l_off;
        const uint32_t aL = aH + ATILE;
        const uint32_t bH = st + 2 * ATILE + (uint32_t)(wc * 32 * ASTR) + b_l_off;
        const uint32_t bL = bH + BTILE;

        #pragma unroll
        for (int ks = 0; ks < 4; ks++) {
            const uint32_t kb = ks * 32;
            uint32_t af[MT][4], bh2[2][4];
            #pragma unroll
            for (int mt = 0; mt < MT; mt++) ldsm4(af[mt], aH + (uint32_t)(mt * 16 * ASTR) + kb);
            #pragma unroll
            for (int np = 0; np < 2; np++) ldsm4(bh2[np], bH + (uint32_t)(np * 16 * ASTR) + kb);
            #pragma unroll
            for (int mt = 0; mt < MT; mt++)
                #pragma unroll
                for (int np = 0; np < 2; np++) {
                    mma16816(acc[mt][2 * np],     af[mt], &bh2[np][0]);
                    mma16816(acc[mt][2 * np + 1], af[mt], &bh2[np][2]);
                }
            uint32_t bl2[2][4];
            #pragma unroll
            for (int np = 0; np < 2; np++) ldsm4(bl2[np], bL + (uint32_t)(np * 16 * ASTR) + kb);
            #pragma unroll
            for (int mt = 0; mt < MT; mt++)
                #pragma unroll
                for (int np = 0; np < 2; np++) {
                    mma16816(acc[mt][2 * np],     af[mt], &bl2[np][0]);
                    mma16816(acc[mt][2 * np + 1], af[mt], &bl2[np][2]);
                }
            #pragma unroll
            for (int mt = 0; mt < MT; mt++) ldsm4(af[mt], aL + (uint32_t)(mt * 16 * ASTR) + kb);
            #pragma unroll
            for (int mt = 0; mt < MT; mt++)
                #pragma unroll
                for (int np = 0; np < 2; np++) {
                    mma16816(acc[mt][2 * np],     af[mt], &bh2[np][0]);
                    mma16816(acc[mt][2 * np + 1], af[mt], &bh2[np][2]);
                }
        }
        __syncthreads();
    }

    // ---- epilogue ----
    const int g = lane >> 2, qr = lane & 3;
    const int awidth = aux_hi - aux_lo;
    const float* a0p[MT][2];
    const float* a1p[MT][2];
    #pragma unroll
    for (int mt = 0; mt < MT; mt++)
        #pragma unroll
        for (int hh = 0; hh < 2; hh++) {
            int row = bm + wr * 16 * MT + mt * 16 + g + 8 * hh;
            int rr = (row < M) ? row : 0;
            a0p[mt][hh] = add0 ? add0 + (size_t)idx0[(size_t)rr * idx0s] * add0ld + add0off : nullptr;
            a1p[mt][hh] = add1 ? add1 + (size_t)idx1[(size_t)rr * idx1s] * add1ld + add1off : nullptr;
        }
    #pragma unroll
    for (int nt = 0; nt < 4; nt++) {
        const int col = bn + wc * 32 + nt * 8 + qr * 2;
        float2 bv = make_float2(0.f, 0.f);
        if (bias) bv = *reinterpret_cast<const float2*>(bias + col);
        const bool in_aux = (col >= aux_lo) && (col < aux_hi);
        #pragma unroll
        for (int mt = 0; mt < MT; mt++) {
            #pragma unroll
            for (int hh = 0; hh < 2; hh++) {
                const int row = bm + wr * 16 * MT + mt * 16 + g + 8 * hh;
                if (row >= M) continue;
                float v0 = acc[mt][nt][2 * hh]     + bv.x;
                float v1 = acc[mt][nt][2 * hh + 1] + bv.y;
                if (add0) {
                    float2 a = *reinterpret_cast<const float2*>(a0p[mt][hh] + col);
                    v0 += a.x; v1 += a.y;
                }
                if (add1) {
                    float2 a = *reinterpret_cast<const float2*>(a1p[mt][hh] + col);
                    v0 += a.x; v1 += a.y;
                }
                if (do_relu) { v0 = fmaxf(v0, 0.f); v1 = fmaxf(v1, 0.f); }
                if (Cf && !(skip_mid && in_aux))
                    *reinterpret_cast<float2*>(Cf + (size_t)row * ldc + col) = make_float2(v0, v1);
                if (Ch) {
                    bf16 h0, l0, h1, l1;
                    split1(v0, h0, l0); split1(v1, h1, l1);
                    __nv_bfloat162 ph; ph.x = h0; ph.y = h1;
                    __nv_bfloat162 pl; pl.x = l0; pl.y = l1;
                    *reinterpret_cast<__nv_bfloat162*>(Ch + (size_t)row * ldc + col) = ph;
                    *reinterpret_cast<__nv_bfloat162*>(Cl + (size_t)row * ldc + col) = pl;
                }
                if (in_aux) {
                    const int ac = col - aux_lo;
                    if (auxf)
                        *reinterpret_cast<float2*>(auxf + (size_t)row * awidth + ac) = make_float2(v0, v1);
                    if (auxh) {
                        bf16 h0, l0, h1, l1;
                        split1(v0, h0, l0); split1(v1, h1, l1);
                        __nv_bfloat162 ph; ph.x = h0; ph.y = h1;
                        __nv_bfloat162 pl; pl.x = l0; pl.y = l1;
                        *reinterpret_cast<__nv_bfloat162*>(auxh + (size_t)row * awidth + ac) = ph;
                        *reinterpret_cast<__nv_bfloat162*>(auxl + (size_t)row * awidth + ac) = pl;
                    }
                }
            }
        }
    }
}

// ---------------- mega prep kernels (one launch each) ----------------
struct TsJob { const float* src; bf16* dh; bf16* dl; int K, N, KP, tile0; };
struct TsArgs { TsJob j[32]; int nj; };
__global__ void mega_tsplit_kernel(TsArgs a) {
    const int b = blockIdx.x;
    int lo = 0;
    #pragma unroll 1
    for (int i = 1; i < a.nj; i++) if (a.j[i].tile0 <= b) lo = i;
    const TsJob jb = a.j[lo];
    const int t = b - jb.tile0;
    const int ntx = (jb.KP + 31) >> 5;
    const int tx = t % ntx, ty = t / ntx;
    __shared__ float tile[32][33];
    const int bk = tx * 32, bn = ty * 32;
    const int x = threadIdx.x & 31, y = threadIdx.x >> 5;
    for (int i = y; i < 32; i += 8) {
        int k = bk + i, n = bn + x;
        tile[i][x] = (k < jb.K && n < jb.N) ? jb.src[(size_t)k * jb.N + n] : 0.f;
    }
    __syncthreads();
    for (int i = y; i < 32; i += 8) {
        int n = bn + i, k = bk + x;
        if (n < jb.N && k < jb.KP) {
            float v = tile[x][i];
            bf16 hh, ll; split1(v, hh, ll);
            jb.dh[(size_t)n * jb.KP + k] = hh;
            jb.dl[(size_t)n * jb.KP + k] = ll;
        }
    }
}

struct SpJob { const float* src; bf16* dh; bf16* dl; int W, WP, n, blk0; };
struct SpArgs { SpJob j[4]; int nj; };
__global__ void mega_split_kernel(SpArgs a) {
    const int b = blockIdx.x;
    int lo = 0;
    #pragma unroll 1
    for (int i = 1; i < a.nj; i++) if (a.j[i].blk0 <= b) lo = i;
    const SpJob jb = a.j[lo];
    const int i = (b - jb.blk0) * 256 + threadIdx.x;
    if (i >= jb.n) return;
    const int v = i / jb.WP, c = i - v * jb.WP;
    float val = (c < jb.W) ? jb.src[(size_t)v * jb.W + c] : 0.f;
    bf16 hh, ll; split1(val, hh, ll);
    jb.dh[i] = hh; jb.dl[i] = ll;
}

// ---------------- deterministic scatter-mean pooling ----------------
__global__ void zero_int_kernel(int* p, int n) {
    int i = blockIdx.x * blockDim.x + threadIdx.x;
    if (i < n) p[i] = 0;
}
__global__ void build_count_kernel(const int* __restrict__ rels, int* __restrict__ objarr,
                                   int* __restrict__ cnt) {
    int e = blockIdx.x * blockDim.x + threadIdx.x;
    if (e >= E_N) return;
    int t = e >> 1;
    int v = rels[3 * t + ((e & 1) ? 2 : 0)];
    objarr[e] = v;
    atomicAdd(&cnt[v], 1);
}
__global__ void scan_kernel(const int* __restrict__ cnt, int* __restrict__ off,
                            float* __restrict__ inv) {
    __shared__ int buf[2][2048];
    int tid = threadIdx.x;
    for (int i = tid; i < 2048; i += 1024) {
        int c = (i < O_N) ? cnt[i] : 0;
        buf[0][i] = c;
        if (i < O_N) inv[i] = 1.0f / fmaxf((float)c, 1.0f);
    }
    __syncthreads();
    int src = 0;
    for (int d = 1; d < 2048; d <<= 1) {
        for (int i = tid; i < 2048; i += 1024) {
            int v = buf[src][i];
            if (i >= d) v += buf[src][i - d];
            buf[1 - src][i] = v;
        }
        src = 1 - src;
        __syncthreads();
    }
    for (int i = tid; i < O_N; i += 1024) off[i] = (i == 0) ? 0 : buf[src][i - 1];
    if (tid == 0) off[O_N] = buf[src][O_N - 1];
}
__global__ void rank_fill_kernel(const int* __restrict__ objarr, const int* __restrict__ off,
                                 int* __restrict__ entries) {
    int i = blockIdx.x * blockDim.x + threadIdx.x;
    if (i >= O_N) return;
    int w = off[i];
    for (int e = 0; e < E_N; e++)
        if (objarr[e] == i) entries[w++] = e;
}
__global__ void pool_gather_kernel(const float* __restrict__ t,
                                   const int* __restrict__ entries, const int* __restrict__ off,
                                   const float* __restrict__ inv,
                                   bf16* __restrict__ ph, bf16* __restrict__ pl) {
    int i = blockIdx.x;
    int c0 = threadIdx.x;
    int beg = off[i], end = off[i + 1];
    float s0 = 0.f, s1 = 0.f;
    for (int p = beg; p < end; p++) {
        int e = entries[p];
        int tr = e >> 1;
        const float* src = t + (size_t)tr * 1536 + ((e & 1) ? 1024 : 0);
        s0 += src[c0];
        s1 += src[c0 + 256];
    }
    float iv = inv[i];
    float v0 = s0 * iv, v1 = s1 * iv;
    bf16 h, l;
    split1(v0, h, l);
    ph[(size_t)i * 512 + c0] = h; pl[(size_t)i * 512 + c0] = l;
    split1(v1, h, l);
    ph[(size_t)i * 512 + c0 + 256] = h; pl[(size_t)i * 512 + c0 + 256] = l;
}

// ---------------- host glue ----------------
struct GPtr { bf16 *h, *l; };

#define SMEM_MT4 (2 * (2*128*ASTR + 2*128*ASTR))
#define SMEM_MT2 (2 * (2*64*ASTR + 2*128*ASTR))
#define SMEM_MT1 (2 * (2*32*ASTR + 2*128*ASTR))

struct AddArg { const float* p; const int* idx; int s; int ld; int off; };

static inline void run_mma(int MT, int M, int Ntot, int K, int ldb, int relu,
                           GPtr A0, int lda, GPtr Bt,
                           const float* bias,
                           float* Cf, GPtr C, int ldc,
                           AddArg a0 = {nullptr, nullptr, 0, 0, 0},
                           AddArg a1 = {nullptr, nullptr, 0, 0, 0},
                           float* auxf = nullptr, GPtr aux = {nullptr, nullptr},
                           int aux_lo = 0, int aux_hi = 0, int skip_mid = 0)
{
    if (MT == 4) {
        dim3 grid(Ntot / BN, (M + 127) / 128);
        mma_gemm_kernel<4><<<grid, 256, SMEM_MT4>>>(M, K, ldb, relu, skip_mid,
            A0.h, A0.l, lda, Bt.h, Bt.l, bias,
            a0.p, a0.idx, a0.s, a0.ld, a0.off,
            a1.p, a1.idx, a1.s, a1.ld, a1.off,
            Cf, C.h, C.l, ldc, auxf, aux.h, aux.l, aux_lo, aux_hi);
    } else if (MT == 2) {
        dim3 grid(Ntot / BN, (M + 63) / 64);
        mma_gemm_kernel<2><<<grid, 256, SMEM_MT2>>>(M, K, ldb, relu, skip_mid,
            A0.h, A0.l, lda, Bt.h, Bt.l, bias,
            a0.p, a0.idx, a0.s, a0.ld, a0.off,
            a1.p, a1.idx, a1.s, a1.ld, a1.off,
            Cf, C.h, C.l, ldc, auxf, aux.h, aux.l, aux_lo, aux_hi);
    } else {
        dim3 grid(Ntot / BN, (M + 31) / 32);
        mma_gemm_kernel<1><<<grid, 256, SMEM_MT1>>>(M, K, ldb, relu, skip_mid,
            A0.h, A0.l, lda, Bt.h, Bt.l, bias,
            a0.p, a0.idx, a0.s, a0.ld, a0.off,
            a1.p, a1.idx, a1.s, a1.ld, a1.off,
            Cf, C.h, C.l, ldc, auxf, aux.h, aux.l, aux_lo, aux_hi);
    }
}

extern "C" void kernel_launch(void* const* d_in, const int* in_sizes, int n_in,
                              void* d_out, int out_size)
{
    const float* obj_embs  = (const float*)d_in[0];
    const float* pred_embs = (const float*)d_in[2];
    const int*   rels      = (const int*)d_in[4];
    const int*   objs      = (const int*)d_in[5];
    const float* obj_table = (const float*)d_in[6];
    const float* rel_table = (const float*)d_in[7];
    const float* Wf_obj    = (const float*)d_in[8];
    const float* bf_obj    = (const float*)d_in[9];
    const float* Wf_rel    = (const float*)d_in[10];
    const float* bf_rel    = (const float*)d_in[11];
    const float* W1a       = (const float*)d_in[12];
    const float* b1a       = (const float*)d_in[13];
    const float* W1b       = (const float*)d_in[14];
    const float* b1b       = (const float*)d_in[15];
    const float* W2a       = (const float*)d_in[16];
    const float* b2a       = (const float*)d_in[17];
    const float* W2b       = (const float*)d_in[18];
    const float* b2b       = (const float*)d_in[19];
    const float* Ws1a      = (const float*)d_in[20];
    const float* bs1a      = (const float*)d_in[21];
    const float* Ws1b      = (const float*)d_in[22];
    const float* bs1b      = (const float*)d_in[23];
    const float* Ws2a      = (const float*)d_in[24];
    const float* bs2a      = (const float*)d_in[25];
    const float* Ws2b      = (const float*)d_in[26];
    const float* bs2b      = (const float*)d_in[27];
    float* out = (float*)d_out;

    cudaFuncSetAttribute(mma_gemm_kernel<4>, cudaFuncAttributeMaxDynamicSharedMemorySize, SMEM_MT4);
    cudaFuncSetAttribute(mma_gemm_kernel<2>, cudaFuncAttributeMaxDynamicSharedMemorySize, SMEM_MT2);
    cudaFuncSetAttribute(mma_gemm_kernel<1>, cudaFuncAttributeMaxDynamicSharedMemorySize, SMEM_MT1);

    auto sym = [](const void* s) { void* p; cudaGetSymbolAddress(&p, s); return p; };
    GPtr eobj  = {(bf16*)sym(g_eobj_h),  (bf16*)sym(g_eobj_l)};
    GPtr epred = {(bf16*)sym(g_epred_h), (bf16*)sym(g_epred_l)};
    GPtr tobj  = {(bf16*)sym(g_tobj_h),  (bf16*)sym(g_tobj_l)};
    GPtr trel  = {(bf16*)sym(g_trel_h),  (bf16*)sym(g_trel_l)};
    GPtr objA  = {(bf16*)sym(g_objA_h),  (bf16*)sym(g_objA_l)};
    GPtr pA    = {(bf16*)sym(g_pA_h),    (bf16*)sym(g_pA_l)};
    GPtr hb    = {(bf16*)sym(g_h_h),     (bf16*)sym(g_h_l)};
    GPtr p512  = {(bf16*)sym(g_p512_h),  (bf16*)sym(g_p512_l)};
    GPtr pool  = {(bf16*)sym(g_pool_h),  (bf16*)sym(g_pool_l)};
    GPtr o512  = {(bf16*)sym(g_o512_h),  (bf16*)sym(g_o512_l)};
    float* tblobj = (float*)sym(g_tblobj);
    float* tblrel = (float*)sym(g_tblrel);
    float* objSO  = (float*)sym(g_objSO);
    bf16* wth = (bf16*)sym(g_wt_h);
    bf16* wtl = (bf16*)sym(g_wt_l);
    float* tbuf = (float*)sym(g_t);
    int* cnt = (int*)sym(g_cnt);
    int* off = (int*)sym(g_off);
    int* objarr = (int*)sym(g_objarr);
    int* entries = (int*)sym(g_entries);
    float* finv = (float*)sym(g_inv);

    // weight pool (bf16 elems)
    size_t po = 0;
    auto take = [&](size_t n) { GPtr r = {wth + po, wtl + po}; po += n; return r; };
    GPtr tWfobj  = take((size_t)DIN * KP_EMB);
    GPtr tWfrel  = take((size_t)DIN * KP_EMB);
    GPtr tW1a_p  = take((size_t)H_DIM * DIN);
    GPtr tW1a_so = take((size_t)1024 * DIN);
    GPtr tW1b    = take((size_t)1536 * H_DIM);
    GPtr tW2a    = take((size_t)H_DIM * H_DIM);
    GPtr tW2b    = take((size_t)DG * H_DIM);
    GPtr tWs1a_p  = take((size_t)L_EXTRA * H_DIM * DG);
    GPtr tWs1a_so = take((size_t)L_EXTRA * 1024 * DG);
    GPtr tWs1b    = take((size_t)L_EXTRA * 1536 * H_DIM);
    GPtr tWs2a    = take((size_t)L_EXTRA * H_DIM * H_DIM);
    GPtr tWs2b    = take((size_t)L_EXTRA * DG * H_DIM);

    // --- mega prep: all weight transpose+splits in ONE launch ---
    TsArgs ta; ta.nj = 0;
    int tile0 = 0;
    auto addts = [&](const float* src, GPtr dst, int K, int N, int KP) {
        TsJob& j = ta.j[ta.nj++];
        j.src = src; j.dh = dst.h; j.dl = dst.l; j.K = K; j.N = N; j.KP = KP; j.tile0 = tile0;
        tile0 += ((KP + 31) / 32) * ((N + 31) / 32);
    };
    addts(Wf_obj, tWfobj, DIN + DW, DIN, KP_EMB);
    addts(Wf_rel, tWfrel, DIN + DW, DIN, KP_EMB);
    addts(W1a + (size_t)DIN * H_DIM, tW1a_p, DIN, H_DIM, DIN);
    addts(W1a, tW1a_so, DIN, H_DIM, DIN);
    addts(W1a + (size_t)2 * DIN * H_DIM, {tW1a_so.h + (size_t)H_DIM * DIN, tW1a_so.l + (size_t)H_DIM * DIN}, DIN, H_DIM, DIN);
    addts(W1b, tW1b, H_DIM, 1536, H_DIM);
    addts(W2a, tW2a, H_DIM, H_DIM, H_DIM);
    addts(W2b, tW2b, H_DIM, DG, H_DIM);
    for (int i = 0; i < L_EXTRA; i++) {
        const float* Wi = Ws1a + (size_t)i * 3 * DG * H_DIM;
        GPtr p_i  = {tWs1a_p.h + (size_t)i * H_DIM * DG,  tWs1a_p.l + (size_t)i * H_DIM * DG};
        GPtr so_i = {tWs1a_so.h + (size_t)i * 1024 * DG,  tWs1a_so.l + (size_t)i * 1024 * DG};
        addts(Wi + (size_t)DG * H_DIM, p_i, DG, H_DIM, DG);
        addts(Wi, so_i, DG, H_DIM, DG);
        addts(Wi + (size_t)2 * DG * H_DIM, {so_i.h + (size_t)H_DIM * DG, so_i.l + (size_t)H_DIM * DG}, DG, H_DIM, DG);
        addts(Ws1b + (size_t)i * H_DIM * 1536, {tWs1b.h + (size_t)i * 1536 * H_DIM, tWs1b.l + (size_t)i * 1536 * H_DIM}, H_DIM, 1536, H_DIM);
        addts(Ws2a + (size_t)i * H_DIM * H_DIM, {tWs2a.h + (size_t)i * H_DIM * H_DIM, tWs2a.l + (size_t)i * H_DIM * H_DIM}, H_DIM, H_DIM, H_DIM);
        addts(Ws2b + (size_t)i * H_DIM * DG, {tWs2b.h + (size_t)i * DG * H_DIM, tWs2b.l + (size_t)i * DG * H_DIM}, H_DIM, DG, H_DIM);
    }
    mega_tsplit_kernel<<<tile0, 256>>>(ta);

    // --- mega activation splits in ONE launch ---
    SpArgs sa; sa.nj = 0;
    int blk0 = 0;
    auto addsp = [&](const float* src, GPtr dst, int V, int W, int WP) {
        SpJob& j = sa.j[sa.nj++];
        j.src = src; j.dh = dst.h; j.dl = dst.l; j.W = W; j.WP = WP; j.n = V * WP; j.blk0 = blk0;
        blk0 += (V * WP + 255) / 256;
    };
    addsp(obj_embs, eobj, O_N, DIN, DIN);
    addsp(pred_embs, epred, T_N, DIN, DIN);
    addsp(obj_table, tobj, 1000, DW, DWP);
    addsp(rel_table, trel, 500, DW, DWP);
    mega_split_kernel<<<blk0, 256>>>(sa);

    // --- CSR for deterministic pooling ---
    zero_int_kernel<<<(O_N + 255) / 256, 256>>>(cnt, O_N);
    build_count_kernel<<<(E_N + 255) / 256, 256>>>(rels, objarr, cnt);
    scan_kernel<<<1, 1024>>>(cnt, off, finv);
    rank_fill_kernel<<<(O_N + 255) / 256, 256>>>(objarr, off, entries);

    GPtr nullg = {nullptr, nullptr};
    AddArg noadd = {nullptr, nullptr, 0, 0, 0};

    // --- table contributions ---
    run_mma(2, 1000, DIN, DWP, KP_EMB, 0, tobj, DWP,
            {tWfobj.h + DIN, tWfobj.l + DIN}, nullptr, tblobj, nullg, DIN);
    run_mma(1, 500, DIN, DWP, KP_EMB, 0, trel, DWP,
            {tWfrel.h + DIN, tWfrel.l + DIN}, nullptr, tblrel, nullg, DIN);

    // --- embedding GEMMs ---
    run_mma(4, O_N, DIN, DIN, KP_EMB, 1, eobj, DIN, tWfobj, bf_obj,
            nullptr, objA, DIN, {tblobj, objs, 1, DIN, 0});
    run_mma(4, T_N, DIN, DIN, KP_EMB, 1, epred, DIN, tWfrel, bf_rel,
            nullptr, pA, DIN, {tblrel, rels + 1, 3, DIN, 0});

    // --- layer 0 ---
    run_mma(2, O_N, 1024, DIN, DIN, 0, objA, DIN, tW1a_so, nullptr,
            objSO, nullg, 1024);
    run_mma(2, T_N, H_DIM, DIN, DIN, 1, pA, DIN, tW1a_p, b1a,
            nullptr, hb, H_DIM,
            {objSO, rels, 3, 1024, 0}, {objSO, rels + 2, 3, 1024, 512});
    run_mma(4, T_N, 1536, H_DIM, H_DIM, 1, hb, H_DIM, tW1b, b1b,
            tbuf, nullg, 1536, noadd, noadd, nullptr, p512, 512, 1024, 1);
    pool_gather_kernel<<<O_N, 256>>>(tbuf, entries, off, finv, pool.h, pool.l);
    run_mma(1, O_N, H_DIM, H_DIM, H_DIM, 1, pool, 512, tW2a, b2a,
            nullptr, hb, H_DIM);
    run_mma(1, O_N, DG, H_DIM, H_DIM, 1, hb, 512, tW2b, b2b,
            nullptr, o512, DG);

    // --- extra layers ---
    for (int i = 0; i < L_EXTRA; i++) {
        const bool last = (i == L_EXTRA - 1);
        GPtr p_i  = {tWs1a_p.h + (size_t)i * H_DIM * DG,  tWs1a_p.l + (size_t)i * H_DIM * DG};
        GPtr so_i = {tWs1a_so.h + (size_t)i * 1024 * DG,  tWs1a_so.l + (size_t)i * 1024 * DG};
        GPtr w1b = {tWs1b.h + (size_t)i * 1536 * H_DIM,   tWs1b.l + (size_t)i * 1536 * H_DIM};
        GPtr w2a = {tWs2a.h + (size_t)i * H_DIM * H_DIM,  tWs2a.l + (size_t)i * H_DIM * H_DIM};
        GPtr w2b = {tWs2b.h + (size_t)i * DG * H_DIM,     tWs2b.l + (size_t)i * DG * H_DIM};

        run_mma(2, O_N, 1024, DG, DG, 0, o512, DG, so_i, nullptr,
                objSO, nullg, 1024);
        run_mma(2, T_N, H_DIM, DG, DG, 1, p512, DG, p_i, bs1a + (size_t)i * H_DIM,
                nullptr, hb, H_DIM,
                {objSO, rels, 3, 1024, 0}, {objSO, rels + 2, 3, 1024, 512});
        run_mma(4, T_N, 1536, H_DIM, H_DIM, 1, hb, H_DIM, w1b, bs1b + (size_t)i * 1536,
                tbuf, nullg, 1536, noadd, noadd,
                last ? (out + (size_t)O_N * DG) : nullptr,
                last ? nullg : p512, 512, 1024, 1);
        pool_gather_kernel<<<O_N, 256>>>(tbuf, entries, off, finv, pool.h, pool.l);
        run_mma(1, O_N, H_DIM, H_DIM, H_DIM, 1, pool, 512, w2a, bs2a + (size_t)i * H_DIM,
                nullptr, hb, H_DIM);
        run_mma(1, O_N, DG, H_DIM, H_DIM, 1, hb, 512, w2b, bs2b + (size_t)i * DG,
                last ? out : nullptr, last ? nullg : o512, DG);
    }
}